// round 12
// baseline (speedup 1.0000x reference)
#include <cuda_runtime.h>
#include <cuda_bf16.h>

// B=4,C=128,H=W=64,L=4096, D=64, DI=128, N=16, R=4, K=4. bb=branch*4+b (8), bbk=bb*4+k (32)
// scan: 32 chunks x 128 steps

__device__ float g_xd  [4*128*4096];
__device__ float g_xc  [8*4096*128];
__device__ float g_z   [8*4096*128];
__device__ float g_xc2 [8*4096*128];
__device__ float g_dts [32*4096*4];
__device__ float g_bc  [32*4096*32];
__device__ float g_hc  [32*32*128*16];
__device__ float g_cp  [32*32*128*16];
__device__ float g_hi  [32*32*128*16];
__device__ float g_y4  [32*4096*128];
__device__ float g_g   [8*4096*128];
__device__ float g_xo  [4*128*4096];
__device__ float g_A   [8192];      // -exp(A_logs) * log2(e)
__device__ float g_dsum[128];

#define L2E 1.4426950408889634f
#define LN2 0.6931471805599453f

__device__ __forceinline__ int pos_map(int k, int t){
    int tt = (k >= 2) ? (4095 - t) : t;
    if (k & 1) tt = ((tt & 63) << 6) | (tt >> 6);
    return tt;
}

// K1: depthwise 3x3 on x (NCHW), smem-tiled; also does prep.
// grid 2048 = (plane, strip4), 256 thr
__global__ void k1_dwconv(const float* __restrict__ x, const float* __restrict__ w,
                          const float* __restrict__ b, const float* __restrict__ A_logs,
                          const float* __restrict__ Ds){
    int gi = blockIdx.x*256 + threadIdx.x;
    if (gi < 8192) g_A[gi] = -expf(A_logs[gi]) * L2E;
    if (gi < 128)  g_dsum[gi] = Ds[gi] + Ds[128+gi] + Ds[256+gi] + Ds[384+gi];

    int plane = blockIdx.x >> 2, strip = blockIdx.x & 3;
    int c = plane & 127, h0 = strip*16;
    __shared__ float t[18][64];
    const float* xp = x + (size_t)plane*4096;
    for (int i=threadIdx.x; i<1152; i+=256){
        int r = i >> 6, ww = i & 63, hh = h0-1+r;
        t[r][ww] = ((unsigned)hh < 64u) ? xp[hh*64+ww] : 0.f;
    }
    __syncthreads();
    float w9[9];
    #pragma unroll
    for (int i=0;i<9;i++) w9[i] = w[c*9+i];
    float bv = b[c];
    float* op = g_xd + (size_t)plane*4096 + h0*64;
    for (int i=threadIdx.x; i<1024; i+=256){
        int r = i >> 6, ww = i & 63;
        float acc = bv;
        #pragma unroll
        for (int dh=0; dh<3; dh++){
            #pragma unroll
            for (int dw=-1; dw<=1; dw++){
                int w2 = ww+dw;
                if ((unsigned)w2 < 64u) acc = fmaf(t[r+dh][w2], w9[dh*3+dw+1], acc);
            }
        }
        op[i] = acc;
    }
}

// K3: fused LN(64) + in_proj GEMM [32768,64]x[64,256], 128x128 tile, 8x8/thread.
// grid (256,2), 256 thr
__global__ void k3_inproj(const float* __restrict__ ipw, const float* __restrict__ g1,
                          const float* __restrict__ b1){
    __shared__ float As[32][132];
    __shared__ float Ws[32][132];
    __shared__ float smu[128], srs[128];
    __shared__ float ps[256], pq[256];
    int row0 = blockIdx.x*128, jh = blockIdx.y, tid = threadIdx.x;
    int bb = row0 >> 12, l0 = row0 & 4095;
    int br = bb >> 2, bi = bb & 3;
    const float* src = g_xd + (size_t)(bi*128 + br*64)*4096 + l0;
    {
        int r = tid & 127, half = tid >> 7;
        float s=0.f, ss=0.f;
        #pragma unroll 8
        for (int c=half*32; c<half*32+32; c++){
            float v = src[(size_t)c*4096 + r];
            s += v; ss += v*v;
        }
        ps[tid]=s; pq[tid]=ss;
    }
    __syncthreads();
    if (tid < 128){
        float st = ps[tid]+ps[tid+128], sst = pq[tid]+pq[tid+128];
        float m = st*(1.f/64.f);
        smu[tid]=m; srs[tid]=rsqrtf(sst*(1.f/64.f)-m*m+1e-5f);
    }
    __syncthreads();
    int ct = tid & 15, rt = tid >> 4;
    float acc[8][8];
    #pragma unroll
    for (int i=0;i<8;i++)
        #pragma unroll
        for (int j=0;j<8;j++) acc[i][j]=0.f;
    #pragma unroll
    for (int kc=0; kc<2; kc++){
        for (int idx=tid; idx<4096; idx+=256){
            int c = idx >> 7, r = idx & 127;
            int cg = kc*32 + c;
            As[c][r] = (src[(size_t)cg*4096 + r]-smu[r])*srs[r]*g1[cg] + b1[cg];
        }
        for (int idx=tid; idx<4096; idx+=256){
            int j = idx >> 5, c = idx & 31;
            Ws[c][j] = ipw[(jh*128+j)*64 + kc*32 + c];
        }
        __syncthreads();
        #pragma unroll 4
        for (int c=0;c<32;c++){
            float4 a0 = *(const float4*)&As[c][rt*4];
            float4 a1 = *(const float4*)&As[c][rt*4+64];
            float4 w0 = *(const float4*)&Ws[c][ct*4];
            float4 w1 = *(const float4*)&Ws[c][ct*4+64];
            float ar[8] = {a0.x,a0.y,a0.z,a0.w,a1.x,a1.y,a1.z,a1.w};
            float wr[8] = {w0.x,w0.y,w0.z,w0.w,w1.x,w1.y,w1.z,w1.w};
            #pragma unroll
            for (int i=0;i<8;i++)
                #pragma unroll
                for (int j=0;j<8;j++) acc[i][j] = fmaf(ar[i], wr[j], acc[i][j]);
        }
        __syncthreads();
    }
    float* dstbase = (jh==0) ? g_xc : g_z;
    #pragma unroll
    for (int ri=0;ri<8;ri++){
        int r = row0 + rt*4 + (ri&3) + (ri>>2)*64;
        #pragma unroll
        for (int jj=0;jj<2;jj++){
            float4 v = make_float4(acc[ri][jj*4],acc[ri][jj*4+1],acc[ri][jj*4+2],acc[ri][jj*4+3]);
            *(float4*)&dstbase[(size_t)r*128 + ct*4 + jj*64] = v;
        }
    }
}

// K4: depthwise 3x3 + SiLU on xc (pixel-major), smem-tiled by c-group.
// grid 512 = (bb8, strip8, cg8), 256 thr
__global__ void k4_conv(const float* __restrict__ cw, const float* __restrict__ cb){
    int bb = blockIdx.x >> 6;
    int strip = (blockIdx.x >> 3) & 7;
    int cg = blockIdx.x & 7;
    int h0 = strip*8, c0 = cg*16;
    __shared__ float t[10][64][16];
    const float* src = g_xc + (size_t)bb*4096*128 + c0;
    for (int i=threadIdx.x; i<10240; i+=256){
        int cl = i & 15, ww = (i>>4) & 63, r = i >> 10;
        int hh = h0-1+r;
        t[r][ww][cl] = ((unsigned)hh < 64u) ? src[(size_t)(hh*64+ww)*128 + cl] : 0.f;
    }
    __syncthreads();
    int cl = threadIdx.x & 15, c = c0 + cl;
    float w9[9];
    #pragma unroll
    for (int i=0;i<9;i++) w9[i] = cw[c*9+i];
    float bv = cb[c];
    float* dst = g_xc2 + (size_t)bb*4096*128 + c0 + cl;
    for (int i=threadIdx.x; i<8192; i+=256){
        int ww = (i>>4) & 63, r = i >> 10;
        float acc = bv;
        #pragma unroll
        for (int dh=0; dh<3; dh++){
            #pragma unroll
            for (int dw=-1; dw<=1; dw++){
                int w2 = ww+dw;
                if ((unsigned)w2 < 64u) acc = fmaf(t[r+dh][w2][cl], w9[dh*3+dw+1], acc);
            }
        }
        acc = acc/(1.f+__expf(-acc));
        dst[(size_t)((h0+r)*64+ww)*128] = acc;
    }
}

// K5: x_proj for k-pair {kp, kp+2}, 256 rows x 72 outs per block, 8x8/thread,
// kc-chunk 32. grid 256 = (bb8, kp2, tile16), 288 thr
__global__ void k5_xdbl(const float* __restrict__ xpw){
    __shared__ float Xt[32][260];
    __shared__ float Wt[32][76];
    int bb = blockIdx.x >> 5;
    int kp = (blockIdx.x >> 4) & 1;
    int tile = blockIdx.x & 15;
    int tid = threadIdx.x;
    int t0 = tile*256;
    int ct = tid % 9, rt = tid / 9;   // rt 0..31
    float acc[8][8];
    #pragma unroll
    for (int i=0;i<8;i++)
        #pragma unroll
        for (int j=0;j<8;j++) acc[i][j]=0.f;
    #pragma unroll
    for (int kc=0; kc<4; kc++){
        for (int idx=tid; idx<8192; idx+=288){
            int tl = idx >> 5, c = idx & 31;
            int l = t0 + tl;
            int p = kp ? (((l & 63) << 6) | (l >> 6)) : l;
            Xt[c][tl] = g_xc2[((size_t)bb*4096 + p)*128 + kc*32 + c];
        }
        for (int idx=tid; idx<2304; idx+=288){
            int o = idx >> 5, c = idx & 31;
            int kk = (o < 36) ? kp : (kp+2);
            int oo = (o < 36) ? o : (o-36);
            Wt[c][o] = xpw[(kk*36+oo)*128 + kc*32 + c];
        }
        __syncthreads();
        #pragma unroll 4
        for (int c=0;c<32;c++){
            float4 x0 = *(const float4*)&Xt[c][rt*8];
            float4 x1 = *(const float4*)&Xt[c][rt*8+4];
            float4 w0 = *(const float4*)&Wt[c][ct*8];
            float4 w1 = *(const float4*)&Wt[c][ct*8+4];
            float xr[8] = {x0.x,x0.y,x0.z,x0.w,x1.x,x1.y,x1.z,x1.w};
            float wr[8] = {w0.x,w0.y,w0.z,w0.w,w1.x,w1.y,w1.z,w1.w};
            #pragma unroll
            for (int i=0;i<8;i++)
                #pragma unroll
                for (int j=0;j<8;j++) acc[i][j] = fmaf(xr[i], wr[j], acc[i][j]);
        }
        __syncthreads();
    }
    #pragma unroll
    for (int i=0;i<8;i++){
        int tl = rt*8 + i;
        #pragma unroll
        for (int gj=0; gj<2; gj++){
            int o4 = ct*8 + gj*4;
            float4 v = make_float4(acc[i][gj*4],acc[i][gj*4+1],acc[i][gj*4+2],acc[i][gj*4+3]);
            int khi = (o4 >= 36);
            int t = khi ? (4095-(t0+tl)) : (t0+tl);
            int bbk = bb*4 + kp + (khi ? 2 : 0);
            int oo = khi ? (o4-36) : o4;
            if (oo == 0)
                *(float4*)&g_dts[((size_t)bbk*4096 + t)*4] = v;
            else
                *(float4*)&g_bc[((size_t)bbk*4096 + t)*32 + (oo-4)] = v;
        }
    }
}

// K6a: pass1 chunk-local scan (128 steps), exp2-domain, prefetch.
// warp=(bbk,dg,chunk32). grid 2048, 256 thr
__global__ void k6a_scan1(const float* __restrict__ dtw, const float* __restrict__ dtb){
    int gw = blockIdx.x*8 + (threadIdx.x >> 5);
    int lane = threadIdx.x & 31;
    int chunk = gw & 31, dg = (gw >> 5) & 15, bbk = gw >> 9;
    int bb = bbk >> 2, k = bbk & 3;
    int dl = lane >> 2, sg = lane & 3, d = dg*8 + dl;
    float4 Av = *(const float4*)(g_A + (size_t)(k*128+d)*16 + sg*4);   // pre-scaled by L2E
    float4 wv = *(const float4*)(dtw + (k*128+d)*4);
    wv.x *= L2E; wv.y *= L2E; wv.z *= L2E; wv.w *= L2E;
    float bvb = dtb[k*128+d] * L2E;
    float h0=0,h1=0,h2=0,h3=0, dsum=0;
    int t0c = chunk*128;
    const float4* dts4 = (const float4*)(g_dts + ((size_t)bbk*4096 + t0c)*4);
    const float* bc  = g_bc + ((size_t)bbk*4096 + t0c)*32 + sg*4;
    const float* ubb = g_xc2 + (size_t)bb*4096*128 + d;
    float4 qn = dts4[sg];
    float un = ubb[(size_t)pos_map(k, t0c + sg)*128];
    for (int g4=0; g4<32; g4++){
        float4 q = qn; float uu = un;
        if (g4 < 31){
            qn = dts4[(g4+1)*4 + sg];
            un = ubb[(size_t)pos_map(k, t0c + (g4+1)*4 + sg)*128];
        }
        float x2 = q.x*wv.x + q.y*wv.y + q.z*wv.z + q.w*wv.w + bvb;   // log2 domain
        float sp = (x2 > 28.85f) ? x2*LN2 : LN2*__log2f(1.f+exp2f(x2));
        float duu = sp * uu;
        #pragma unroll
        for (int j=0;j<4;j++){
            int t = g4*4 + j;
            float delta = __shfl_sync(0xffffffffu, sp, j, 4);
            float du    = __shfl_sync(0xffffffffu, duu, j, 4);
            float4 B = *(const float4*)(bc + (size_t)t*32);
            dsum += delta;
            float a0 = exp2f(delta*Av.x), a1 = exp2f(delta*Av.y);
            float a2 = exp2f(delta*Av.z), a3 = exp2f(delta*Av.w);
            h0 = fmaf(a0,h0,du*B.x); h1 = fmaf(a1,h1,du*B.y);
            h2 = fmaf(a2,h2,du*B.z); h3 = fmaf(a3,h3,du*B.w);
        }
    }
    size_t so = ((size_t)(bbk*32+chunk)*128 + d)*16 + sg*4;
    *(float4*)(g_hc + so) = make_float4(h0,h1,h2,h3);
    *(float4*)(g_cp + so) = make_float4(exp2f(dsum*Av.x),exp2f(dsum*Av.y),
                                        exp2f(dsum*Av.z),exp2f(dsum*Av.w));
}

// K6b: sequential scan over 32 chunk summaries, loads prefetched. grid 256, 256 thr
__global__ void k6b_scan2(){
    int idx = blockIdx.x*256 + threadIdx.x;
    int bbk = idx >> 11, rem = idx & 2047;
    size_t base = (size_t)bbk*32*2048 + rem;
    float H = 0.f;
    float cp = g_cp[base], hc = g_hc[base];
    #pragma unroll
    for (int c=0; c<32; c++){
        size_t o = base + (size_t)c*2048;
        float cpn = 0.f, hcn = 0.f;
        if (c < 31){ cpn = g_cp[o+2048]; hcn = g_hc[o+2048]; }
        g_hi[o] = H;
        H = fmaf(cp, H, hc);
        cp = cpn; hc = hcn;
    }
}

// K6c: pass3 with incoming state, emit y=C.h, exp2-domain, prefetch. grid 2048, 256 thr
__global__ void k6c_scan3(const float* __restrict__ dtw, const float* __restrict__ dtb){
    int gw = blockIdx.x*8 + (threadIdx.x >> 5);
    int lane = threadIdx.x & 31;
    int chunk = gw & 31, dg = (gw >> 5) & 15, bbk = gw >> 9;
    int bb = bbk >> 2, k = bbk & 3;
    int dl = lane >> 2, sg = lane & 3, d = dg*8 + dl;
    float4 Av = *(const float4*)(g_A + (size_t)(k*128+d)*16 + sg*4);
    float4 wv = *(const float4*)(dtw + (k*128+d)*4);
    wv.x *= L2E; wv.y *= L2E; wv.z *= L2E; wv.w *= L2E;
    float bvb = dtb[k*128+d] * L2E;
    size_t so = ((size_t)(bbk*32+chunk)*128 + d)*16 + sg*4;
    float4 hi = *(const float4*)(g_hi + so);
    float h0=hi.x, h1=hi.y, h2=hi.z, h3=hi.w;
    int t0c = chunk*128;
    const float4* dts4 = (const float4*)(g_dts + ((size_t)bbk*4096 + t0c)*4);
    const float* bc  = g_bc + ((size_t)bbk*4096 + t0c)*32;
    const float* ubb = g_xc2 + (size_t)bb*4096*128 + d;
    float* yo = g_y4 + ((size_t)bbk*4096 + t0c)*128 + d;
    float4 qn = dts4[sg];
    float un = ubb[(size_t)pos_map(k, t0c + sg)*128];
    for (int g4=0; g4<32; g4++){
        float4 q = qn; float uu = un;
        if (g4 < 31){
            qn = dts4[(g4+1)*4 + sg];
            un = ubb[(size_t)pos_map(k, t0c + (g4+1)*4 + sg)*128];
        }
        float x2 = q.x*wv.x + q.y*wv.y + q.z*wv.z + q.w*wv.w + bvb;
        float sp = (x2 > 28.85f) ? x2*LN2 : LN2*__log2f(1.f+exp2f(x2));
        float duu = sp * uu;
        #pragma unroll
        for (int j=0;j<4;j++){
            int t = g4*4 + j;
            float delta = __shfl_sync(0xffffffffu, sp, j, 4);
            float du    = __shfl_sync(0xffffffffu, duu, j, 4);
            float4 B = *(const float4*)(bc + (size_t)t*32 + sg*4);
            float4 C = *(const float4*)(bc + (size_t)t*32 + 16 + sg*4);
            float a0 = exp2f(delta*Av.x), a1 = exp2f(delta*Av.y);
            float a2 = exp2f(delta*Av.z), a3 = exp2f(delta*Av.w);
            h0 = fmaf(a0,h0,du*B.x); h1 = fmaf(a1,h1,du*B.y);
            h2 = fmaf(a2,h2,du*B.z); h3 = fmaf(a3,h3,du*B.w);
            float acc = h0*C.x + h1*C.y + h2*C.z + h3*C.w;
            acc += __shfl_xor_sync(0xffffffffu, acc, 1);
            acc += __shfl_xor_sync(0xffffffffu, acc, 2);
            if (sg == 0) yo[(size_t)t*128] = acc;
        }
    }
}

// K7: combine 4 dirs + Dsum*u + LN(128) + silu(z) gate, float4 lanes.
// warp/pixel. grid 4096, 256 thr
__global__ void k7_comb(const float* __restrict__ ong, const float* __restrict__ onb){
    int wid = threadIdx.x >> 5, lane = threadIdx.x & 31;
    int gp = blockIdx.x*8 + wid;
    int bb = gp >> 12, l = gp & 4095;
    float4 v = *(const float4*)&g_dsum[lane*4];
    float4 xr = *(const float4*)&g_xc2[((size_t)bb*4096 + l)*128 + lane*4];
    v.x *= xr.x; v.y *= xr.y; v.z *= xr.z; v.w *= xr.w;
    #pragma unroll
    for (int k=0;k<4;k++){
        int t = pos_map(k,l);
        float4 r = *(const float4*)&g_y4[(((size_t)(bb*4+k)*4096 + t)*128) + lane*4];
        v.x += r.x; v.y += r.y; v.z += r.z; v.w += r.w;
    }
    float s = v.x+v.y+v.z+v.w;
    float ss = v.x*v.x+v.y*v.y+v.z*v.z+v.w*v.w;
    #pragma unroll
    for (int o=16;o;o>>=1){ s += __shfl_xor_sync(0xffffffffu,s,o); ss += __shfl_xor_sync(0xffffffffu,ss,o); }
    float mu = s*(1.f/128.f);
    float rs = rsqrtf(ss*(1.f/128.f)-mu*mu+1e-5f);
    float4 z4 = *(const float4*)&g_z[((size_t)bb*4096+l)*128 + lane*4];
    float4 gg = *(const float4*)&ong[lane*4];
    float4 bb4 = *(const float4*)&onb[lane*4];
    float4 o4;
    o4.x = ((v.x-mu)*rs*gg.x+bb4.x) * (z4.x/(1.f+__expf(-z4.x)));
    o4.y = ((v.y-mu)*rs*gg.y+bb4.y) * (z4.y/(1.f+__expf(-z4.y)));
    o4.z = ((v.z-mu)*rs*gg.z+bb4.z) * (z4.z/(1.f+__expf(-z4.z)));
    o4.w = ((v.w-mu)*rs*gg.w+bb4.w) * (z4.w/(1.f+__expf(-z4.w)));
    *(float4*)&g_g[((size_t)bb*4096+l)*128 + lane*4] = o4;
}

// K8: out_proj [32768,128]x[128,64] + residual -> NCHW. 128x64 tile, 8x4/thread,
// K-chunk 32. grid 256, 256 thr
__global__ void k8_outproj(const float* __restrict__ opw, const float* __restrict__ scale){
    __shared__ float Xs[32][132];
    __shared__ float Ws[32][72];
    int row0 = blockIdx.x*128, tid = threadIdx.x;
    int ct = tid & 15, rt = tid >> 4;
    float acc[8][4];
    #pragma unroll
    for (int i=0;i<8;i++)
        #pragma unroll
        for (int j=0;j<4;j++) acc[i][j]=0.f;
    #pragma unroll
    for (int kc=0; kc<4; kc++){
        for (int idx=tid; idx<4096; idx+=256){
            int r = idx >> 5, c = idx & 31;
            Xs[c][r] = g_g[(size_t)(row0+r)*128 + kc*32 + c];
        }
        for (int idx=tid; idx<2048; idx+=256){
            int j = idx >> 5, c = idx & 31;
            Ws[c][j] = opw[j*128 + kc*32 + c];
        }
        __syncthreads();
        #pragma unroll 4
        for (int c=0;c<32;c++){
            float4 x0 = *(const float4*)&Xs[c][rt*4];
            float4 x1 = *(const float4*)&Xs[c][rt*4+64];
            float4 w0 = *(const float4*)&Ws[c][ct*4];
            float xr[8] = {x0.x,x0.y,x0.z,x0.w,x1.x,x1.y,x1.z,x1.w};
            float wr[4] = {w0.x,w0.y,w0.z,w0.w};
            #pragma unroll
            for (int i=0;i<8;i++)
                #pragma unroll
                for (int j=0;j<4;j++) acc[i][j] = fmaf(xr[i], wr[j], acc[i][j]);
        }
        __syncthreads();
    }
    float s1 = scale[0] + 1.f;
    int bb = row0 >> 12, l0 = (row0 & 4095) + rt*4;
    #pragma unroll
    for (int jo=0;jo<4;jo++){
        int j = ct*4 + jo;
        int plane = (bb&3)*128 + (bb>>2)*64 + j;
        #pragma unroll
        for (int half=0; half<2; half++){
            int l = l0 + half*64;
            float4 xd4 = *(const float4*)(g_xd + (size_t)plane*4096 + l);
            float4 o4;
            o4.x = fmaf(s1, xd4.x, acc[half*4+0][jo]);
            o4.y = fmaf(s1, xd4.y, acc[half*4+1][jo]);
            o4.z = fmaf(s1, xd4.z, acc[half*4+2][jo]);
            o4.w = fmaf(s1, xd4.w, acc[half*4+3][jo]);
            *(float4*)(g_xo + (size_t)plane*4096 + l) = o4;
        }
    }
}

// K9: instance norm over HW + leaky relu. grid 512 planes, 256 thr
__global__ void k9_inorm(const float* __restrict__ gamma, const float* __restrict__ beta,
                         float* __restrict__ out){
    __shared__ float buf[4096];
    __shared__ float rsum[8], rsq[8];
    int plane = blockIdx.x, cch = plane & 127;
    const float* src = g_xo + (size_t)plane*4096;
    float s=0.f, ss=0.f;
    for (int idx=threadIdx.x; idx<1024; idx+=256){
        float4 v = ((const float4*)src)[idx];
        ((float4*)buf)[idx] = v;
        s += v.x+v.y+v.z+v.w;
        ss += v.x*v.x+v.y*v.y+v.z*v.z+v.w*v.w;
    }
    #pragma unroll
    for (int o=16;o;o>>=1){ s += __shfl_xor_sync(0xffffffffu,s,o); ss += __shfl_xor_sync(0xffffffffu,ss,o); }
    int wid = threadIdx.x >> 5;
    if ((threadIdx.x & 31) == 0){ rsum[wid]=s; rsq[wid]=ss; }
    __syncthreads();
    if (threadIdx.x == 0){
        float ts=0.f, tss=0.f;
        #pragma unroll
        for (int i=0;i<8;i++){ ts += rsum[i]; tss += rsq[i]; }
        float mu = ts*(1.f/4096.f);
        rsum[0] = mu;
        rsq[0]  = rsqrtf(tss*(1.f/4096.f)-mu*mu+1e-5f);
    }
    __syncthreads();
    float mu = rsum[0], rr = rsq[0];
    float gm = gamma[cch], bt = beta[cch];
    float* dst = out + (size_t)plane*4096;
    for (int idx=threadIdx.x; idx<4096; idx+=256){
        float v = (buf[idx]-mu)*rr*gm + bt;
        dst[idx] = v > 0.f ? v : 0.01f*v;
    }
}

extern "C" void kernel_launch(void* const* d_in, const int* in_sizes, int n_in,
                              void* d_out, int out_size) {
    const float* x        = (const float*)d_in[0];
    const float* dw_w     = (const float*)d_in[1];
    const float* dw_b     = (const float*)d_in[2];
    const float* scale    = (const float*)d_in[3];
    const float* ln1_g    = (const float*)d_in[4];
    const float* ln1_b    = (const float*)d_in[5];
    const float* in_proj  = (const float*)d_in[6];
    const float* conv_w   = (const float*)d_in[7];
    const float* conv_b   = (const float*)d_in[8];
    const float* x_proj   = (const float*)d_in[9];
    const float* dt_w     = (const float*)d_in[10];
    const float* dt_b     = (const float*)d_in[11];
    const float* A_logs   = (const float*)d_in[12];
    const float* Ds       = (const float*)d_in[13];
    const float* on_g     = (const float*)d_in[14];
    const float* on_b     = (const float*)d_in[15];
    const float* out_proj = (const float*)d_in[16];
    const float* in_gamma = (const float*)d_in[17];
    const float* in_beta  = (const float*)d_in[18];
    float* out = (float*)d_out;

    k1_dwconv  <<<2048, 256>>>(x, dw_w, dw_b, A_logs, Ds);
    k3_inproj  <<<dim3(256,2), 256>>>(in_proj, ln1_g, ln1_b);
    k4_conv    <<<512, 256>>>(conv_w, conv_b);
    k5_xdbl    <<<256, 288>>>(x_proj);
    k6a_scan1  <<<2048, 256>>>(dt_w, dt_b);
    k6b_scan2  <<<256, 256>>>();
    k6c_scan3  <<<2048, 256>>>(dt_w, dt_b);
    k7_comb    <<<4096, 256>>>(on_g, on_b);
    k8_outproj <<<256, 256>>>(out_proj, scale);
    k9_inorm   <<<512, 256>>>(in_gamma, in_beta, out);
}

// round 13
// speedup vs baseline: 1.0147x; 1.0147x over previous
#include <cuda_runtime.h>
#include <cuda_bf16.h>

// B=4,C=128,H=W=64,L=4096, D=64, DI=128, N=16, R=4, K=4. bb=branch*4+b (8), bbk=bb*4+k (32)
// scan: 32 chunks x 128 steps

__device__ float g_xd  [4*128*4096];
__device__ float g_xc  [8*4096*128];
__device__ float g_z   [8*4096*128];
__device__ float g_xc2 [8*4096*128];
__device__ float g_dts [32*4096*4];
__device__ float g_bc  [32*4096*32];
__device__ float g_hc  [32*32*128*16];
__device__ float g_cp  [32*32*128*16];
__device__ float g_hi  [32*32*128*16];
__device__ float g_y4  [32*4096*128];
__device__ float g_g   [8*4096*128];
__device__ float g_xo  [4*128*4096];
__device__ float g_A   [8192];      // -exp(A_logs) * log2(e)
__device__ float g_dsum[128];

#define L2E 1.4426950408889634f
#define LN2 0.6931471805599453f

__device__ __forceinline__ int pos_map(int k, int t){
    int tt = (k >= 2) ? (4095 - t) : t;
    if (k & 1) tt = ((tt & 63) << 6) | (tt >> 6);
    return tt;
}

// K1: depthwise 3x3 on x (NCHW), smem-tiled; also does prep.
// grid 2048 = (plane, strip4), 256 thr
__global__ void k1_dwconv(const float* __restrict__ x, const float* __restrict__ w,
                          const float* __restrict__ b, const float* __restrict__ A_logs,
                          const float* __restrict__ Ds){
    int gi = blockIdx.x*256 + threadIdx.x;
    if (gi < 8192) g_A[gi] = -expf(A_logs[gi]) * L2E;
    if (gi < 128)  g_dsum[gi] = Ds[gi] + Ds[128+gi] + Ds[256+gi] + Ds[384+gi];

    int plane = blockIdx.x >> 2, strip = blockIdx.x & 3;
    int c = plane & 127, h0 = strip*16;
    __shared__ float t[18][64];
    const float* xp = x + (size_t)plane*4096;
    for (int i=threadIdx.x; i<1152; i+=256){
        int r = i >> 6, ww = i & 63, hh = h0-1+r;
        t[r][ww] = ((unsigned)hh < 64u) ? xp[hh*64+ww] : 0.f;
    }
    __syncthreads();
    float w9[9];
    #pragma unroll
    for (int i=0;i<9;i++) w9[i] = w[c*9+i];
    float bv = b[c];
    float* op = g_xd + (size_t)plane*4096 + h0*64;
    for (int i=threadIdx.x; i<1024; i+=256){
        int r = i >> 6, ww = i & 63;
        float acc = bv;
        #pragma unroll
        for (int dh=0; dh<3; dh++){
            #pragma unroll
            for (int dw=-1; dw<=1; dw++){
                int w2 = ww+dw;
                if ((unsigned)w2 < 64u) acc = fmaf(t[r+dh][w2], w9[dh*3+dw+1], acc);
            }
        }
        op[i] = acc;
    }
}

// K3: fused LN(64) + in_proj GEMM [32768,64]x[64,256], 128x128 tile, 8x8/thread.
// grid (256,2), 256 thr
__global__ void k3_inproj(const float* __restrict__ ipw, const float* __restrict__ g1,
                          const float* __restrict__ b1){
    __shared__ float As[32][132];
    __shared__ float Ws[32][132];
    __shared__ float smu[128], srs[128];
    __shared__ float ps[256], pq[256];
    int row0 = blockIdx.x*128, jh = blockIdx.y, tid = threadIdx.x;
    int bb = row0 >> 12, l0 = row0 & 4095;
    int br = bb >> 2, bi = bb & 3;
    const float* src = g_xd + (size_t)(bi*128 + br*64)*4096 + l0;
    {
        int r = tid & 127, half = tid >> 7;
        float s=0.f, ss=0.f;
        #pragma unroll 8
        for (int c=half*32; c<half*32+32; c++){
            float v = src[(size_t)c*4096 + r];
            s += v; ss += v*v;
        }
        ps[tid]=s; pq[tid]=ss;
    }
    __syncthreads();
    if (tid < 128){
        float st = ps[tid]+ps[tid+128], sst = pq[tid]+pq[tid+128];
        float m = st*(1.f/64.f);
        smu[tid]=m; srs[tid]=rsqrtf(sst*(1.f/64.f)-m*m+1e-5f);
    }
    __syncthreads();
    int ct = tid & 15, rt = tid >> 4;
    float acc[8][8];
    #pragma unroll
    for (int i=0;i<8;i++)
        #pragma unroll
        for (int j=0;j<8;j++) acc[i][j]=0.f;
    #pragma unroll
    for (int kc=0; kc<2; kc++){
        for (int idx=tid; idx<4096; idx+=256){
            int c = idx >> 7, r = idx & 127;
            int cg = kc*32 + c;
            As[c][r] = (src[(size_t)cg*4096 + r]-smu[r])*srs[r]*g1[cg] + b1[cg];
        }
        for (int idx=tid; idx<4096; idx+=256){
            int j = idx >> 5, c = idx & 31;
            Ws[c][j] = ipw[(jh*128+j)*64 + kc*32 + c];
        }
        __syncthreads();
        #pragma unroll 4
        for (int c=0;c<32;c++){
            float4 a0 = *(const float4*)&As[c][rt*4];
            float4 a1 = *(const float4*)&As[c][rt*4+64];
            float4 w0 = *(const float4*)&Ws[c][ct*4];
            float4 w1 = *(const float4*)&Ws[c][ct*4+64];
            float ar[8] = {a0.x,a0.y,a0.z,a0.w,a1.x,a1.y,a1.z,a1.w};
            float wr[8] = {w0.x,w0.y,w0.z,w0.w,w1.x,w1.y,w1.z,w1.w};
            #pragma unroll
            for (int i=0;i<8;i++)
                #pragma unroll
                for (int j=0;j<8;j++) acc[i][j] = fmaf(ar[i], wr[j], acc[i][j]);
        }
        __syncthreads();
    }
    float* dstbase = (jh==0) ? g_xc : g_z;
    #pragma unroll
    for (int ri=0;ri<8;ri++){
        int r = row0 + rt*4 + (ri&3) + (ri>>2)*64;
        #pragma unroll
        for (int jj=0;jj<2;jj++){
            float4 v = make_float4(acc[ri][jj*4],acc[ri][jj*4+1],acc[ri][jj*4+2],acc[ri][jj*4+3]);
            *(float4*)&dstbase[(size_t)r*128 + ct*4 + jj*64] = v;
        }
    }
}

// K4: depthwise 3x3 + SiLU on xc (pixel-major), smem-tiled by c-group.
// grid 512 = (bb8, strip8, cg8), 256 thr
__global__ void k4_conv(const float* __restrict__ cw, const float* __restrict__ cb){
    int bb = blockIdx.x >> 6;
    int strip = (blockIdx.x >> 3) & 7;
    int cg = blockIdx.x & 7;
    int h0 = strip*8, c0 = cg*16;
    __shared__ float t[10][64][16];
    const float* src = g_xc + (size_t)bb*4096*128 + c0;
    for (int i=threadIdx.x; i<10240; i+=256){
        int cl = i & 15, ww = (i>>4) & 63, r = i >> 10;
        int hh = h0-1+r;
        t[r][ww][cl] = ((unsigned)hh < 64u) ? src[(size_t)(hh*64+ww)*128 + cl] : 0.f;
    }
    __syncthreads();
    int cl = threadIdx.x & 15, c = c0 + cl;
    float w9[9];
    #pragma unroll
    for (int i=0;i<9;i++) w9[i] = cw[c*9+i];
    float bv = cb[c];
    float* dst = g_xc2 + (size_t)bb*4096*128 + c0 + cl;
    for (int i=threadIdx.x; i<8192; i+=256){
        int ww = (i>>4) & 63, r = i >> 10;
        float acc = bv;
        #pragma unroll
        for (int dh=0; dh<3; dh++){
            #pragma unroll
            for (int dw=-1; dw<=1; dw++){
                int w2 = ww+dw;
                if ((unsigned)w2 < 64u) acc = fmaf(t[r+dh][w2][cl], w9[dh*3+dw+1], acc);
            }
        }
        acc = acc/(1.f+__expf(-acc));
        dst[(size_t)((h0+r)*64+ww)*128] = acc;
    }
}

// K5: x_proj for k-pair {kp, kp+2} sharing one X tile. Tile 128 rows x 72 outs,
// thread = 8 rows x 4 outs. grid 512 = (bb8, kp2, tile32), 288 thr  (R11 version)
__global__ void k5_xdbl(const float* __restrict__ xpw){
    __shared__ float Xt[64][132];
    __shared__ float Wt[64][76];
    int bb = blockIdx.x >> 6;
    int kp = (blockIdx.x >> 5) & 1;
    int tile = blockIdx.x & 31;
    int tid = threadIdx.x;
    int t0 = tile*128;
    int ct = tid % 18, rt = tid / 18;
    float acc[8][4];
    #pragma unroll
    for (int i=0;i<8;i++)
        #pragma unroll
        for (int j=0;j<4;j++) acc[i][j]=0.f;
    #pragma unroll
    for (int kc=0; kc<2; kc++){
        for (int idx=tid; idx<8192; idx+=288){
            int tl = idx >> 6, c = idx & 63;
            int l = t0 + tl;
            int p = kp ? (((l & 63) << 6) | (l >> 6)) : l;
            Xt[c][tl] = g_xc2[((size_t)bb*4096 + p)*128 + kc*64 + c];
        }
        for (int idx=tid; idx<4608; idx+=288){
            int o = idx >> 6, c = idx & 63;
            int kk = (o < 36) ? kp : (kp+2);
            int oo = (o < 36) ? o : (o-36);
            Wt[c][o] = xpw[(kk*36+oo)*128 + kc*64 + c];
        }
        __syncthreads();
        #pragma unroll 4
        for (int c=0;c<64;c++){
            float4 x0 = *(const float4*)&Xt[c][rt*8];
            float4 x1 = *(const float4*)&Xt[c][rt*8+4];
            float4 wv = *(const float4*)&Wt[c][ct*4];
            float xr[8] = {x0.x,x0.y,x0.z,x0.w,x1.x,x1.y,x1.z,x1.w};
            float wr[4] = {wv.x,wv.y,wv.z,wv.w};
            #pragma unroll
            for (int i=0;i<8;i++)
                #pragma unroll
                for (int j=0;j<4;j++) acc[i][j] = fmaf(xr[i], wr[j], acc[i][j]);
        }
        __syncthreads();
    }
    bool hi = (ct >= 9);
    int o4 = hi ? (ct-9)*4 : ct*4;
    int bbk = bb*4 + kp + (hi ? 2 : 0);
    #pragma unroll
    for (int i=0;i<8;i++){
        int tl = rt*8 + i;
        int t = hi ? (4095 - (t0+tl)) : (t0+tl);
        float4 v = make_float4(acc[i][0],acc[i][1],acc[i][2],acc[i][3]);
        if (o4 == 0)
            *(float4*)&g_dts[((size_t)bbk*4096 + t)*4] = v;
        else
            *(float4*)&g_bc[((size_t)bbk*4096 + t)*32 + (o4-4)] = v;
    }
}

// K6a: pass1 chunk-local scan (128 steps), exp2-domain, prefetch.
// warp=(bbk,dg,chunk32). grid 2048, 256 thr
__global__ void k6a_scan1(const float* __restrict__ dtw, const float* __restrict__ dtb){
    int gw = blockIdx.x*8 + (threadIdx.x >> 5);
    int lane = threadIdx.x & 31;
    int chunk = gw & 31, dg = (gw >> 5) & 15, bbk = gw >> 9;
    int bb = bbk >> 2, k = bbk & 3;
    int dl = lane >> 2, sg = lane & 3, d = dg*8 + dl;
    float4 Av = *(const float4*)(g_A + (size_t)(k*128+d)*16 + sg*4);   // pre-scaled by L2E
    float4 wv = *(const float4*)(dtw + (k*128+d)*4);
    wv.x *= L2E; wv.y *= L2E; wv.z *= L2E; wv.w *= L2E;
    float bvb = dtb[k*128+d] * L2E;
    float h0=0,h1=0,h2=0,h3=0, dsum=0;
    int t0c = chunk*128;
    const float4* dts4 = (const float4*)(g_dts + ((size_t)bbk*4096 + t0c)*4);
    const float* bc  = g_bc + ((size_t)bbk*4096 + t0c)*32 + sg*4;
    const float* ubb = g_xc2 + (size_t)bb*4096*128 + d;
    float4 qn = dts4[sg];
    float un = ubb[(size_t)pos_map(k, t0c + sg)*128];
    for (int g4=0; g4<32; g4++){
        float4 q = qn; float uu = un;
        if (g4 < 31){
            qn = dts4[(g4+1)*4 + sg];
            un = ubb[(size_t)pos_map(k, t0c + (g4+1)*4 + sg)*128];
        }
        float x2 = q.x*wv.x + q.y*wv.y + q.z*wv.z + q.w*wv.w + bvb;   // log2 domain
        float sp = (x2 > 28.85f) ? x2*LN2 : LN2*__log2f(1.f+exp2f(x2));
        float duu = sp * uu;
        #pragma unroll
        for (int j=0;j<4;j++){
            int t = g4*4 + j;
            float delta = __shfl_sync(0xffffffffu, sp, j, 4);
            float du    = __shfl_sync(0xffffffffu, duu, j, 4);
            float4 B = *(const float4*)(bc + (size_t)t*32);
            dsum += delta;
            float a0 = exp2f(delta*Av.x), a1 = exp2f(delta*Av.y);
            float a2 = exp2f(delta*Av.z), a3 = exp2f(delta*Av.w);
            h0 = fmaf(a0,h0,du*B.x); h1 = fmaf(a1,h1,du*B.y);
            h2 = fmaf(a2,h2,du*B.z); h3 = fmaf(a3,h3,du*B.w);
        }
    }
    size_t so = ((size_t)(bbk*32+chunk)*128 + d)*16 + sg*4;
    *(float4*)(g_hc + so) = make_float4(h0,h1,h2,h3);
    *(float4*)(g_cp + so) = make_float4(exp2f(dsum*Av.x),exp2f(dsum*Av.y),
                                        exp2f(dsum*Av.z),exp2f(dsum*Av.w));
}

// K6b: sequential scan over 32 chunk summaries, loads prefetched. grid 256, 256 thr
__global__ void k6b_scan2(){
    int idx = blockIdx.x*256 + threadIdx.x;
    int bbk = idx >> 11, rem = idx & 2047;
    size_t base = (size_t)bbk*32*2048 + rem;
    float H = 0.f;
    float cp = g_cp[base], hc = g_hc[base];
    #pragma unroll
    for (int c=0; c<32; c++){
        size_t o = base + (size_t)c*2048;
        float cpn = 0.f, hcn = 0.f;
        if (c < 31){ cpn = g_cp[o+2048]; hcn = g_hc[o+2048]; }
        g_hi[o] = H;
        H = fmaf(cp, H, hc);
        cp = cpn; hc = hcn;
    }
}

// K6c: pass3 with incoming state, emit y=C.h, exp2-domain, prefetch. grid 2048, 256 thr
__global__ void k6c_scan3(const float* __restrict__ dtw, const float* __restrict__ dtb){
    int gw = blockIdx.x*8 + (threadIdx.x >> 5);
    int lane = threadIdx.x & 31;
    int chunk = gw & 31, dg = (gw >> 5) & 15, bbk = gw >> 9;
    int bb = bbk >> 2, k = bbk & 3;
    int dl = lane >> 2, sg = lane & 3, d = dg*8 + dl;
    float4 Av = *(const float4*)(g_A + (size_t)(k*128+d)*16 + sg*4);
    float4 wv = *(const float4*)(dtw + (k*128+d)*4);
    wv.x *= L2E; wv.y *= L2E; wv.z *= L2E; wv.w *= L2E;
    float bvb = dtb[k*128+d] * L2E;
    size_t so = ((size_t)(bbk*32+chunk)*128 + d)*16 + sg*4;
    float4 hi = *(const float4*)(g_hi + so);
    float h0=hi.x, h1=hi.y, h2=hi.z, h3=hi.w;
    int t0c = chunk*128;
    const float4* dts4 = (const float4*)(g_dts + ((size_t)bbk*4096 + t0c)*4);
    const float* bc  = g_bc + ((size_t)bbk*4096 + t0c)*32;
    const float* ubb = g_xc2 + (size_t)bb*4096*128 + d;
    float* yo = g_y4 + ((size_t)bbk*4096 + t0c)*128 + d;
    float4 qn = dts4[sg];
    float un = ubb[(size_t)pos_map(k, t0c + sg)*128];
    for (int g4=0; g4<32; g4++){
        float4 q = qn; float uu = un;
        if (g4 < 31){
            qn = dts4[(g4+1)*4 + sg];
            un = ubb[(size_t)pos_map(k, t0c + (g4+1)*4 + sg)*128];
        }
        float x2 = q.x*wv.x + q.y*wv.y + q.z*wv.z + q.w*wv.w + bvb;
        float sp = (x2 > 28.85f) ? x2*LN2 : LN2*__log2f(1.f+exp2f(x2));
        float duu = sp * uu;
        #pragma unroll
        for (int j=0;j<4;j++){
            int t = g4*4 + j;
            float delta = __shfl_sync(0xffffffffu, sp, j, 4);
            float du    = __shfl_sync(0xffffffffu, duu, j, 4);
            float4 B = *(const float4*)(bc + (size_t)t*32 + sg*4);
            float4 C = *(const float4*)(bc + (size_t)t*32 + 16 + sg*4);
            float a0 = exp2f(delta*Av.x), a1 = exp2f(delta*Av.y);
            float a2 = exp2f(delta*Av.z), a3 = exp2f(delta*Av.w);
            h0 = fmaf(a0,h0,du*B.x); h1 = fmaf(a1,h1,du*B.y);
            h2 = fmaf(a2,h2,du*B.z); h3 = fmaf(a3,h3,du*B.w);
            float acc = h0*C.x + h1*C.y + h2*C.z + h3*C.w;
            acc += __shfl_xor_sync(0xffffffffu, acc, 1);
            acc += __shfl_xor_sync(0xffffffffu, acc, 2);
            if (sg == 0) yo[(size_t)t*128] = acc;
        }
    }
}

// K7: combine 4 dirs + Dsum*u + LN(128) + silu(z) gate, float4 lanes.
// warp/pixel. grid 4096, 256 thr
__global__ void k7_comb(const float* __restrict__ ong, const float* __restrict__ onb){
    int wid = threadIdx.x >> 5, lane = threadIdx.x & 31;
    int gp = blockIdx.x*8 + wid;
    int bb = gp >> 12, l = gp & 4095;
    float4 v = *(const float4*)&g_dsum[lane*4];
    float4 xr = *(const float4*)&g_xc2[((size_t)bb*4096 + l)*128 + lane*4];
    v.x *= xr.x; v.y *= xr.y; v.z *= xr.z; v.w *= xr.w;
    #pragma unroll
    for (int k=0;k<4;k++){
        int t = pos_map(k,l);
        float4 r = *(const float4*)&g_y4[(((size_t)(bb*4+k)*4096 + t)*128) + lane*4];
        v.x += r.x; v.y += r.y; v.z += r.z; v.w += r.w;
    }
    float s = v.x+v.y+v.z+v.w;
    float ss = v.x*v.x+v.y*v.y+v.z*v.z+v.w*v.w;
    #pragma unroll
    for (int o=16;o;o>>=1){ s += __shfl_xor_sync(0xffffffffu,s,o); ss += __shfl_xor_sync(0xffffffffu,ss,o); }
    float mu = s*(1.f/128.f);
    float rs = rsqrtf(ss*(1.f/128.f)-mu*mu+1e-5f);
    float4 z4 = *(const float4*)&g_z[((size_t)bb*4096+l)*128 + lane*4];
    float4 gg = *(const float4*)&ong[lane*4];
    float4 bb4 = *(const float4*)&onb[lane*4];
    float4 o4;
    o4.x = ((v.x-mu)*rs*gg.x+bb4.x) * (z4.x/(1.f+__expf(-z4.x)));
    o4.y = ((v.y-mu)*rs*gg.y+bb4.y) * (z4.y/(1.f+__expf(-z4.y)));
    o4.z = ((v.z-mu)*rs*gg.z+bb4.z) * (z4.z/(1.f+__expf(-z4.z)));
    o4.w = ((v.w-mu)*rs*gg.w+bb4.w) * (z4.w/(1.f+__expf(-z4.w)));
    *(float4*)&g_g[((size_t)bb*4096+l)*128 + lane*4] = o4;
}

// K8: out_proj [32768,128]x[128,64] + residual -> NCHW. 128x64 tile, 8x4/thread,
// K-chunk 32. grid 256, 256 thr
__global__ void k8_outproj(const float* __restrict__ opw, const float* __restrict__ scale){
    __shared__ float Xs[32][132];
    __shared__ float Ws[32][72];
    int row0 = blockIdx.x*128, tid = threadIdx.x;
    int ct = tid & 15, rt = tid >> 4;
    float acc[8][4];
    #pragma unroll
    for (int i=0;i<8;i++)
        #pragma unroll
        for (int j=0;j<4;j++) acc[i][j]=0.f;
    #pragma unroll
    for (int kc=0; kc<4; kc++){
        for (int idx=tid; idx<4096; idx+=256){
            int r = idx >> 5, c = idx & 31;
            Xs[c][r] = g_g[(size_t)(row0+r)*128 + kc*32 + c];
        }
        for (int idx=tid; idx<2048; idx+=256){
            int j = idx >> 5, c = idx & 31;
            Ws[c][j] = opw[j*128 + kc*32 + c];
        }
        __syncthreads();
        #pragma unroll 4
        for (int c=0;c<32;c++){
            float4 x0 = *(const float4*)&Xs[c][rt*4];
            float4 x1 = *(const float4*)&Xs[c][rt*4+64];
            float4 w0 = *(const float4*)&Ws[c][ct*4];
            float xr[8] = {x0.x,x0.y,x0.z,x0.w,x1.x,x1.y,x1.z,x1.w};
            float wr[4] = {w0.x,w0.y,w0.z,w0.w};
            #pragma unroll
            for (int i=0;i<8;i++)
                #pragma unroll
                for (int j=0;j<4;j++) acc[i][j] = fmaf(xr[i], wr[j], acc[i][j]);
        }
        __syncthreads();
    }
    float s1 = scale[0] + 1.f;
    int bb = row0 >> 12, l0 = (row0 & 4095) + rt*4;
    #pragma unroll
    for (int jo=0;jo<4;jo++){
        int j = ct*4 + jo;
        int plane = (bb&3)*128 + (bb>>2)*64 + j;
        #pragma unroll
        for (int half=0; half<2; half++){
            int l = l0 + half*64;
            float4 xd4 = *(const float4*)(g_xd + (size_t)plane*4096 + l);
            float4 o4;
            o4.x = fmaf(s1, xd4.x, acc[half*4+0][jo]);
            o4.y = fmaf(s1, xd4.y, acc[half*4+1][jo]);
            o4.z = fmaf(s1, xd4.z, acc[half*4+2][jo]);
            o4.w = fmaf(s1, xd4.w, acc[half*4+3][jo]);
            *(float4*)(g_xo + (size_t)plane*4096 + l) = o4;
        }
    }
}

// K9: instance norm over HW + leaky relu. grid 512 planes, 256 thr
__global__ void k9_inorm(const float* __restrict__ gamma, const float* __restrict__ beta,
                         float* __restrict__ out){
    __shared__ float buf[4096];
    __shared__ float rsum[8], rsq[8];
    int plane = blockIdx.x, cch = plane & 127;
    const float* src = g_xo + (size_t)plane*4096;
    float s=0.f, ss=0.f;
    for (int idx=threadIdx.x; idx<1024; idx+=256){
        float4 v = ((const float4*)src)[idx];
        ((float4*)buf)[idx] = v;
        s += v.x+v.y+v.z+v.w;
        ss += v.x*v.x+v.y*v.y+v.z*v.z+v.w*v.w;
    }
    #pragma unroll
    for (int o=16;o;o>>=1){ s += __shfl_xor_sync(0xffffffffu,s,o); ss += __shfl_xor_sync(0xffffffffu,ss,o); }
    int wid = threadIdx.x >> 5;
    if ((threadIdx.x & 31) == 0){ rsum[wid]=s; rsq[wid]=ss; }
    __syncthreads();
    if (threadIdx.x == 0){
        float ts=0.f, tss=0.f;
        #pragma unroll
        for (int i=0;i<8;i++){ ts += rsum[i]; tss += rsq[i]; }
        float mu = ts*(1.f/4096.f);
        rsum[0] = mu;
        rsq[0]  = rsqrtf(tss*(1.f/4096.f)-mu*mu+1e-5f);
    }
    __syncthreads();
    float mu = rsum[0], rr = rsq[0];
    float gm = gamma[cch], bt = beta[cch];
    float* dst = out + (size_t)plane*4096;
    for (int idx=threadIdx.x; idx<4096; idx+=256){
        float v = (buf[idx]-mu)*rr*gm + bt;
        dst[idx] = v > 0.f ? v : 0.01f*v;
    }
}

extern "C" void kernel_launch(void* const* d_in, const int* in_sizes, int n_in,
                              void* d_out, int out_size) {
    const float* x        = (const float*)d_in[0];
    const float* dw_w     = (const float*)d_in[1];
    const float* dw_b     = (const float*)d_in[2];
    const float* scale    = (const float*)d_in[3];
    const float* ln1_g    = (const float*)d_in[4];
    const float* ln1_b    = (const float*)d_in[5];
    const float* in_proj  = (const float*)d_in[6];
    const float* conv_w   = (const float*)d_in[7];
    const float* conv_b   = (const float*)d_in[8];
    const float* x_proj   = (const float*)d_in[9];
    const float* dt_w     = (const float*)d_in[10];
    const float* dt_b     = (const float*)d_in[11];
    const float* A_logs   = (const float*)d_in[12];
    const float* Ds       = (const float*)d_in[13];
    const float* on_g     = (const float*)d_in[14];
    const float* on_b     = (const float*)d_in[15];
    const float* out_proj = (const float*)d_in[16];
    const float* in_gamma = (const float*)d_in[17];
    const float* in_beta  = (const float*)d_in[18];
    float* out = (float*)d_out;

    k1_dwconv  <<<2048, 256>>>(x, dw_w, dw_b, A_logs, Ds);
    k3_inproj  <<<dim3(256,2), 256>>>(in_proj, ln1_g, ln1_b);
    k4_conv    <<<512, 256>>>(conv_w, conv_b);
    k5_xdbl    <<<512, 288>>>(x_proj);
    k6a_scan1  <<<2048, 256>>>(dt_w, dt_b);
    k6b_scan2  <<<256, 256>>>();
    k6c_scan3  <<<2048, 256>>>(dt_w, dt_b);
    k7_comb    <<<4096, 256>>>(on_g, on_b);
    k8_outproj <<<256, 256>>>(out_proj, scale);
    k9_inorm   <<<512, 256>>>(in_gamma, in_beta, out);
}

// round 14
// speedup vs baseline: 1.1397x; 1.1231x over previous
#include <cuda_runtime.h>
#include <cuda_bf16.h>

// B=4,C=128,H=W=64,L=4096, D=64, DI=128, N=16, R=4, K=4. bb=branch*4+b (8), bbk=bb*4+k (32)
// scan: 32 chunks x 128 steps

__device__ float g_xd  [4*128*4096];
__device__ float g_xc  [8*4096*128];
__device__ float g_z   [8*4096*128];
__device__ float g_xc2 [8*4096*128];
__device__ float g_dts [32*4096*4];
__device__ float g_bc  [32*4096*32];
__device__ float g_hc  [32*32*128*16];
__device__ float g_cp  [32*32*128*16];
__device__ float g_hi  [32*32*128*16];
__device__ float g_y4  [32*4096*128];
__device__ float g_g   [8*4096*128];
__device__ float g_xo  [4*128*4096];
__device__ float g_A   [8192];      // -exp(A_logs) * log2(e)
__device__ float g_dsum[128];

#define L2E 1.4426950408889634f
#define LN2 0.6931471805599453f

// Raw MUFU exp2 (what __expf lowers to, minus the log2e FMUL)
__device__ __forceinline__ float ex2(float x){
    float y; asm("ex2.approx.ftz.f32 %0, %1;" : "=f"(y) : "f"(x)); return y;
}

__device__ __forceinline__ int pos_map(int k, int t){
    int tt = (k >= 2) ? (4095 - t) : t;
    if (k & 1) tt = ((tt & 63) << 6) | (tt >> 6);
    return tt;
}

// K1: depthwise 3x3 on x (NCHW), smem-tiled; also does prep.
// grid 2048 = (plane, strip4), 256 thr
__global__ void k1_dwconv(const float* __restrict__ x, const float* __restrict__ w,
                          const float* __restrict__ b, const float* __restrict__ A_logs,
                          const float* __restrict__ Ds){
    int gi = blockIdx.x*256 + threadIdx.x;
    if (gi < 8192) g_A[gi] = -expf(A_logs[gi]) * L2E;
    if (gi < 128)  g_dsum[gi] = Ds[gi] + Ds[128+gi] + Ds[256+gi] + Ds[384+gi];

    int plane = blockIdx.x >> 2, strip = blockIdx.x & 3;
    int c = plane & 127, h0 = strip*16;
    __shared__ float t[18][64];
    const float* xp = x + (size_t)plane*4096;
    for (int i=threadIdx.x; i<1152; i+=256){
        int r = i >> 6, ww = i & 63, hh = h0-1+r;
        t[r][ww] = ((unsigned)hh < 64u) ? xp[hh*64+ww] : 0.f;
    }
    __syncthreads();
    float w9[9];
    #pragma unroll
    for (int i=0;i<9;i++) w9[i] = w[c*9+i];
    float bv = b[c];
    float* op = g_xd + (size_t)plane*4096 + h0*64;
    for (int i=threadIdx.x; i<1024; i+=256){
        int r = i >> 6, ww = i & 63;
        float acc = bv;
        #pragma unroll
        for (int dh=0; dh<3; dh++){
            #pragma unroll
            for (int dw=-1; dw<=1; dw++){
                int w2 = ww+dw;
                if ((unsigned)w2 < 64u) acc = fmaf(t[r+dh][w2], w9[dh*3+dw+1], acc);
            }
        }
        op[i] = acc;
    }
}

// K3: fused LN(64) + in_proj GEMM [32768,64]x[64,256], 128x128 tile, 8x8/thread.
// grid (256,2), 256 thr
__global__ void k3_inproj(const float* __restrict__ ipw, const float* __restrict__ g1,
                          const float* __restrict__ b1){
    __shared__ float As[32][132];
    __shared__ float Ws[32][132];
    __shared__ float smu[128], srs[128];
    __shared__ float ps[256], pq[256];
    int row0 = blockIdx.x*128, jh = blockIdx.y, tid = threadIdx.x;
    int bb = row0 >> 12, l0 = row0 & 4095;
    int br = bb >> 2, bi = bb & 3;
    const float* src = g_xd + (size_t)(bi*128 + br*64)*4096 + l0;
    {
        int r = tid & 127, half = tid >> 7;
        float s=0.f, ss=0.f;
        #pragma unroll 8
        for (int c=half*32; c<half*32+32; c++){
            float v = src[(size_t)c*4096 + r];
            s += v; ss += v*v;
        }
        ps[tid]=s; pq[tid]=ss;
    }
    __syncthreads();
    if (tid < 128){
        float st = ps[tid]+ps[tid+128], sst = pq[tid]+pq[tid+128];
        float m = st*(1.f/64.f);
        smu[tid]=m; srs[tid]=rsqrtf(sst*(1.f/64.f)-m*m+1e-5f);
    }
    __syncthreads();
    int ct = tid & 15, rt = tid >> 4;
    float acc[8][8];
    #pragma unroll
    for (int i=0;i<8;i++)
        #pragma unroll
        for (int j=0;j<8;j++) acc[i][j]=0.f;
    #pragma unroll
    for (int kc=0; kc<2; kc++){
        for (int idx=tid; idx<4096; idx+=256){
            int c = idx >> 7, r = idx & 127;
            int cg = kc*32 + c;
            As[c][r] = (src[(size_t)cg*4096 + r]-smu[r])*srs[r]*g1[cg] + b1[cg];
        }
        for (int idx=tid; idx<4096; idx+=256){
            int j = idx >> 5, c = idx & 31;
            Ws[c][j] = ipw[(jh*128+j)*64 + kc*32 + c];
        }
        __syncthreads();
        #pragma unroll 4
        for (int c=0;c<32;c++){
            float4 a0 = *(const float4*)&As[c][rt*4];
            float4 a1 = *(const float4*)&As[c][rt*4+64];
            float4 w0 = *(const float4*)&Ws[c][ct*4];
            float4 w1 = *(const float4*)&Ws[c][ct*4+64];
            float ar[8] = {a0.x,a0.y,a0.z,a0.w,a1.x,a1.y,a1.z,a1.w};
            float wr[8] = {w0.x,w0.y,w0.z,w0.w,w1.x,w1.y,w1.z,w1.w};
            #pragma unroll
            for (int i=0;i<8;i++)
                #pragma unroll
                for (int j=0;j<8;j++) acc[i][j] = fmaf(ar[i], wr[j], acc[i][j]);
        }
        __syncthreads();
    }
    float* dstbase = (jh==0) ? g_xc : g_z;
    #pragma unroll
    for (int ri=0;ri<8;ri++){
        int r = row0 + rt*4 + (ri&3) + (ri>>2)*64;
        #pragma unroll
        for (int jj=0;jj<2;jj++){
            float4 v = make_float4(acc[ri][jj*4],acc[ri][jj*4+1],acc[ri][jj*4+2],acc[ri][jj*4+3]);
            *(float4*)&dstbase[(size_t)r*128 + ct*4 + jj*64] = v;
        }
    }
}

// K4: depthwise 3x3 + SiLU on xc (pixel-major), smem-tiled by c-group.
// grid 512 = (bb8, strip8, cg8), 256 thr
__global__ void k4_conv(const float* __restrict__ cw, const float* __restrict__ cb){
    int bb = blockIdx.x >> 6;
    int strip = (blockIdx.x >> 3) & 7;
    int cg = blockIdx.x & 7;
    int h0 = strip*8, c0 = cg*16;
    __shared__ float t[10][64][16];
    const float* src = g_xc + (size_t)bb*4096*128 + c0;
    for (int i=threadIdx.x; i<10240; i+=256){
        int cl = i & 15, ww = (i>>4) & 63, r = i >> 10;
        int hh = h0-1+r;
        t[r][ww][cl] = ((unsigned)hh < 64u) ? src[(size_t)(hh*64+ww)*128 + cl] : 0.f;
    }
    __syncthreads();
    int cl = threadIdx.x & 15, c = c0 + cl;
    float w9[9];
    #pragma unroll
    for (int i=0;i<9;i++) w9[i] = cw[c*9+i];
    float bv = cb[c];
    float* dst = g_xc2 + (size_t)bb*4096*128 + c0 + cl;
    for (int i=threadIdx.x; i<8192; i+=256){
        int ww = (i>>4) & 63, r = i >> 10;
        float acc = bv;
        #pragma unroll
        for (int dh=0; dh<3; dh++){
            #pragma unroll
            for (int dw=-1; dw<=1; dw++){
                int w2 = ww+dw;
                if ((unsigned)w2 < 64u) acc = fmaf(t[r+dh][w2][cl], w9[dh*3+dw+1], acc);
            }
        }
        acc = acc/(1.f+__expf(-acc));
        dst[(size_t)((h0+r)*64+ww)*128] = acc;
    }
}

// K5: x_proj for k-pair {kp, kp+2} sharing one X tile. Tile 128 rows x 72 outs,
// thread = 8 rows x 4 outs. grid 512 = (bb8, kp2, tile32), 288 thr
__global__ void k5_xdbl(const float* __restrict__ xpw){
    __shared__ float Xt[64][132];
    __shared__ float Wt[64][76];
    int bb = blockIdx.x >> 6;
    int kp = (blockIdx.x >> 5) & 1;
    int tile = blockIdx.x & 31;
    int tid = threadIdx.x;
    int t0 = tile*128;
    int ct = tid % 18, rt = tid / 18;
    float acc[8][4];
    #pragma unroll
    for (int i=0;i<8;i++)
        #pragma unroll
        for (int j=0;j<4;j++) acc[i][j]=0.f;
    #pragma unroll
    for (int kc=0; kc<2; kc++){
        for (int idx=tid; idx<8192; idx+=288){
            int tl = idx >> 6, c = idx & 63;
            int l = t0 + tl;
            int p = kp ? (((l & 63) << 6) | (l >> 6)) : l;
            Xt[c][tl] = g_xc2[((size_t)bb*4096 + p)*128 + kc*64 + c];
        }
        for (int idx=tid; idx<4608; idx+=288){
            int o = idx >> 6, c = idx & 63;
            int kk = (o < 36) ? kp : (kp+2);
            int oo = (o < 36) ? o : (o-36);
            Wt[c][o] = xpw[(kk*36+oo)*128 + kc*64 + c];
        }
        __syncthreads();
        #pragma unroll 4
        for (int c=0;c<64;c++){
            float4 x0 = *(const float4*)&Xt[c][rt*8];
            float4 x1 = *(const float4*)&Xt[c][rt*8+4];
            float4 wv = *(const float4*)&Wt[c][ct*4];
            float xr[8] = {x0.x,x0.y,x0.z,x0.w,x1.x,x1.y,x1.z,x1.w};
            float wr[4] = {wv.x,wv.y,wv.z,wv.w};
            #pragma unroll
            for (int i=0;i<8;i++)
                #pragma unroll
                for (int j=0;j<4;j++) acc[i][j] = fmaf(xr[i], wr[j], acc[i][j]);
        }
        __syncthreads();
    }
    bool hi = (ct >= 9);
    int o4 = hi ? (ct-9)*4 : ct*4;
    int bbk = bb*4 + kp + (hi ? 2 : 0);
    #pragma unroll
    for (int i=0;i<8;i++){
        int tl = rt*8 + i;
        int t = hi ? (4095 - (t0+tl)) : (t0+tl);
        float4 v = make_float4(acc[i][0],acc[i][1],acc[i][2],acc[i][3]);
        if (o4 == 0)
            *(float4*)&g_dts[((size_t)bbk*4096 + t)*4] = v;
        else
            *(float4*)&g_bc[((size_t)bbk*4096 + t)*32 + (o4-4)] = v;
    }
}

// K6a: pass1 chunk-local scan (128 steps), exp2-domain with MUFU intrinsic,
// prefetch. warp=(bbk,dg,chunk32). grid 2048, 256 thr
__global__ void k6a_scan1(const float* __restrict__ dtw, const float* __restrict__ dtb){
    int gw = blockIdx.x*8 + (threadIdx.x >> 5);
    int lane = threadIdx.x & 31;
    int chunk = gw & 31, dg = (gw >> 5) & 15, bbk = gw >> 9;
    int bb = bbk >> 2, k = bbk & 3;
    int dl = lane >> 2, sg = lane & 3, d = dg*8 + dl;
    float4 Av = *(const float4*)(g_A + (size_t)(k*128+d)*16 + sg*4);   // pre-scaled by L2E
    float4 wv = *(const float4*)(dtw + (k*128+d)*4);
    wv.x *= L2E; wv.y *= L2E; wv.z *= L2E; wv.w *= L2E;
    float bvb = dtb[k*128+d] * L2E;
    float h0=0,h1=0,h2=0,h3=0, dsum=0;
    int t0c = chunk*128;
    const float4* dts4 = (const float4*)(g_dts + ((size_t)bbk*4096 + t0c)*4);
    const float* bc  = g_bc + ((size_t)bbk*4096 + t0c)*32 + sg*4;
    const float* ubb = g_xc2 + (size_t)bb*4096*128 + d;
    float4 qn = dts4[sg];
    float un = ubb[(size_t)pos_map(k, t0c + sg)*128];
    for (int g4=0; g4<32; g4++){
        float4 q = qn; float uu = un;
        if (g4 < 31){
            qn = dts4[(g4+1)*4 + sg];
            un = ubb[(size_t)pos_map(k, t0c + (g4+1)*4 + sg)*128];
        }
        float x2 = q.x*wv.x + q.y*wv.y + q.z*wv.z + q.w*wv.w + bvb;   // log2 domain
        float sp = (x2 > 28.85f) ? x2*LN2 : LN2*__log2f(1.f+ex2(x2));
        float duu = sp * uu;
        #pragma unroll
        for (int j=0;j<4;j++){
            int t = g4*4 + j;
            float delta = __shfl_sync(0xffffffffu, sp, j, 4);
            float du    = __shfl_sync(0xffffffffu, duu, j, 4);
            float4 B = *(const float4*)(bc + (size_t)t*32);
            dsum += delta;
            float a0 = ex2(delta*Av.x), a1 = ex2(delta*Av.y);
            float a2 = ex2(delta*Av.z), a3 = ex2(delta*Av.w);
            h0 = fmaf(a0,h0,du*B.x); h1 = fmaf(a1,h1,du*B.y);
            h2 = fmaf(a2,h2,du*B.z); h3 = fmaf(a3,h3,du*B.w);
        }
    }
    size_t so = ((size_t)(bbk*32+chunk)*128 + d)*16 + sg*4;
    *(float4*)(g_hc + so) = make_float4(h0,h1,h2,h3);
    *(float4*)(g_cp + so) = make_float4(ex2(dsum*Av.x),ex2(dsum*Av.y),
                                        ex2(dsum*Av.z),ex2(dsum*Av.w));
}

// K6b: sequential scan over 32 chunk summaries, loads prefetched. grid 256, 256 thr
__global__ void k6b_scan2(){
    int idx = blockIdx.x*256 + threadIdx.x;
    int bbk = idx >> 11, rem = idx & 2047;
    size_t base = (size_t)bbk*32*2048 + rem;
    float H = 0.f;
    float cp = g_cp[base], hc = g_hc[base];
    #pragma unroll
    for (int c=0; c<32; c++){
        size_t o = base + (size_t)c*2048;
        float cpn = 0.f, hcn = 0.f;
        if (c < 31){ cpn = g_cp[o+2048]; hcn = g_hc[o+2048]; }
        g_hi[o] = H;
        H = fmaf(cp, H, hc);
        cp = cpn; hc = hcn;
    }
}

// K6c: pass3 with incoming state, emit y=C.h, exp2-domain MUFU, prefetch.
// grid 2048, 256 thr
__global__ void k6c_scan3(const float* __restrict__ dtw, const float* __restrict__ dtb){
    int gw = blockIdx.x*8 + (threadIdx.x >> 5);
    int lane = threadIdx.x & 31;
    int chunk = gw & 31, dg = (gw >> 5) & 15, bbk = gw >> 9;
    int bb = bbk >> 2, k = bbk & 3;
    int dl = lane >> 2, sg = lane & 3, d = dg*8 + dl;
    float4 Av = *(const float4*)(g_A + (size_t)(k*128+d)*16 + sg*4);
    float4 wv = *(const float4*)(dtw + (k*128+d)*4);
    wv.x *= L2E; wv.y *= L2E; wv.z *= L2E; wv.w *= L2E;
    float bvb = dtb[k*128+d] * L2E;
    size_t so = ((size_t)(bbk*32+chunk)*128 + d)*16 + sg*4;
    float4 hi = *(const float4*)(g_hi + so);
    float h0=hi.x, h1=hi.y, h2=hi.z, h3=hi.w;
    int t0c = chunk*128;
    const float4* dts4 = (const float4*)(g_dts + ((size_t)bbk*4096 + t0c)*4);
    const float* bc  = g_bc + ((size_t)bbk*4096 + t0c)*32;
    const float* ubb = g_xc2 + (size_t)bb*4096*128 + d;
    float* yo = g_y4 + ((size_t)bbk*4096 + t0c)*128 + d;
    float4 qn = dts4[sg];
    float un = ubb[(size_t)pos_map(k, t0c + sg)*128];
    for (int g4=0; g4<32; g4++){
        float4 q = qn; float uu = un;
        if (g4 < 31){
            qn = dts4[(g4+1)*4 + sg];
            un = ubb[(size_t)pos_map(k, t0c + (g4+1)*4 + sg)*128];
        }
        float x2 = q.x*wv.x + q.y*wv.y + q.z*wv.z + q.w*wv.w + bvb;
        float sp = (x2 > 28.85f) ? x2*LN2 : LN2*__log2f(1.f+ex2(x2));
        float duu = sp * uu;
        #pragma unroll
        for (int j=0;j<4;j++){
            int t = g4*4 + j;
            float delta = __shfl_sync(0xffffffffu, sp, j, 4);
            float du    = __shfl_sync(0xffffffffu, duu, j, 4);
            float4 B = *(const float4*)(bc + (size_t)t*32 + sg*4);
            float4 C = *(const float4*)(bc + (size_t)t*32 + 16 + sg*4);
            float a0 = ex2(delta*Av.x), a1 = ex2(delta*Av.y);
            float a2 = ex2(delta*Av.z), a3 = ex2(delta*Av.w);
            h0 = fmaf(a0,h0,du*B.x); h1 = fmaf(a1,h1,du*B.y);
            h2 = fmaf(a2,h2,du*B.z); h3 = fmaf(a3,h3,du*B.w);
            float acc = h0*C.x + h1*C.y + h2*C.z + h3*C.w;
            acc += __shfl_xor_sync(0xffffffffu, acc, 1);
            acc += __shfl_xor_sync(0xffffffffu, acc, 2);
            if (sg == 0) yo[(size_t)t*128] = acc;
        }
    }
}

// K7: combine 4 dirs + Dsum*u + LN(128) + silu(z) gate, float4 lanes.
// warp/pixel. grid 4096, 256 thr
__global__ void k7_comb(const float* __restrict__ ong, const float* __restrict__ onb){
    int wid = threadIdx.x >> 5, lane = threadIdx.x & 31;
    int gp = blockIdx.x*8 + wid;
    int bb = gp >> 12, l = gp & 4095;
    float4 v = *(const float4*)&g_dsum[lane*4];
    float4 xr = *(const float4*)&g_xc2[((size_t)bb*4096 + l)*128 + lane*4];
    v.x *= xr.x; v.y *= xr.y; v.z *= xr.z; v.w *= xr.w;
    #pragma unroll
    for (int k=0;k<4;k++){
        int t = pos_map(k,l);
        float4 r = *(const float4*)&g_y4[(((size_t)(bb*4+k)*4096 + t)*128) + lane*4];
        v.x += r.x; v.y += r.y; v.z += r.z; v.w += r.w;
    }
    float s = v.x+v.y+v.z+v.w;
    float ss = v.x*v.x+v.y*v.y+v.z*v.z+v.w*v.w;
    #pragma unroll
    for (int o=16;o;o>>=1){ s += __shfl_xor_sync(0xffffffffu,s,o); ss += __shfl_xor_sync(0xffffffffu,ss,o); }
    float mu = s*(1.f/128.f);
    float rs = rsqrtf(ss*(1.f/128.f)-mu*mu+1e-5f);
    float4 z4 = *(const float4*)&g_z[((size_t)bb*4096+l)*128 + lane*4];
    float4 gg = *(const float4*)&ong[lane*4];
    float4 bb4 = *(const float4*)&onb[lane*4];
    float4 o4;
    o4.x = ((v.x-mu)*rs*gg.x+bb4.x) * (z4.x/(1.f+__expf(-z4.x)));
    o4.y = ((v.y-mu)*rs*gg.y+bb4.y) * (z4.y/(1.f+__expf(-z4.y)));
    o4.z = ((v.z-mu)*rs*gg.z+bb4.z) * (z4.z/(1.f+__expf(-z4.z)));
    o4.w = ((v.w-mu)*rs*gg.w+bb4.w) * (z4.w/(1.f+__expf(-z4.w)));
    *(float4*)&g_g[((size_t)bb*4096+l)*128 + lane*4] = o4;
}

// K8: out_proj [32768,128]x[128,64] + residual -> NCHW. 128x64 tile, 8x4/thread,
// K-chunk 32. grid 256, 256 thr
__global__ void k8_outproj(const float* __restrict__ opw, const float* __restrict__ scale){
    __shared__ float Xs[32][132];
    __shared__ float Ws[32][72];
    int row0 = blockIdx.x*128, tid = threadIdx.x;
    int ct = tid & 15, rt = tid >> 4;
    float acc[8][4];
    #pragma unroll
    for (int i=0;i<8;i++)
        #pragma unroll
        for (int j=0;j<4;j++) acc[i][j]=0.f;
    #pragma unroll
    for (int kc=0; kc<4; kc++){
        for (int idx=tid; idx<4096; idx+=256){
            int r = idx >> 5, c = idx & 31;
            Xs[c][r] = g_g[(size_t)(row0+r)*128 + kc*32 + c];
        }
        for (int idx=tid; idx<2048; idx+=256){
            int j = idx >> 5, c = idx & 31;
            Ws[c][j] = opw[j*128 + kc*32 + c];
        }
        __syncthreads();
        #pragma unroll 4
        for (int c=0;c<32;c++){
            float4 x0 = *(const float4*)&Xs[c][rt*4];
            float4 x1 = *(const float4*)&Xs[c][rt*4+64];
            float4 w0 = *(const float4*)&Ws[c][ct*4];
            float xr[8] = {x0.x,x0.y,x0.z,x0.w,x1.x,x1.y,x1.z,x1.w};
            float wr[4] = {w0.x,w0.y,w0.z,w0.w};
            #pragma unroll
            for (int i=0;i<8;i++)
                #pragma unroll
                for (int j=0;j<4;j++) acc[i][j] = fmaf(xr[i], wr[j], acc[i][j]);
        }
        __syncthreads();
    }
    float s1 = scale[0] + 1.f;
    int bb = row0 >> 12, l0 = (row0 & 4095) + rt*4;
    #pragma unroll
    for (int jo=0;jo<4;jo++){
        int j = ct*4 + jo;
        int plane = (bb&3)*128 + (bb>>2)*64 + j;
        #pragma unroll
        for (int half=0; half<2; half++){
            int l = l0 + half*64;
            float4 xd4 = *(const float4*)(g_xd + (size_t)plane*4096 + l);
            float4 o4;
            o4.x = fmaf(s1, xd4.x, acc[half*4+0][jo]);
            o4.y = fmaf(s1, xd4.y, acc[half*4+1][jo]);
            o4.z = fmaf(s1, xd4.z, acc[half*4+2][jo]);
            o4.w = fmaf(s1, xd4.w, acc[half*4+3][jo]);
            *(float4*)(g_xo + (size_t)plane*4096 + l) = o4;
        }
    }
}

// K9: instance norm over HW + leaky relu. grid 512 planes, 256 thr
__global__ void k9_inorm(const float* __restrict__ gamma, const float* __restrict__ beta,
                         float* __restrict__ out){
    __shared__ float buf[4096];
    __shared__ float rsum[8], rsq[8];
    int plane = blockIdx.x, cch = plane & 127;
    const float* src = g_xo + (size_t)plane*4096;
    float s=0.f, ss=0.f;
    for (int idx=threadIdx.x; idx<1024; idx+=256){
        float4 v = ((const float4*)src)[idx];
        ((float4*)buf)[idx] = v;
        s += v.x+v.y+v.z+v.w;
        ss += v.x*v.x+v.y*v.y+v.z*v.z+v.w*v.w;
    }
    #pragma unroll
    for (int o=16;o;o>>=1){ s += __shfl_xor_sync(0xffffffffu,s,o); ss += __shfl_xor_sync(0xffffffffu,ss,o); }
    int wid = threadIdx.x >> 5;
    if ((threadIdx.x & 31) == 0){ rsum[wid]=s; rsq[wid]=ss; }
    __syncthreads();
    if (threadIdx.x == 0){
        float ts=0.f, tss=0.f;
        #pragma unroll
        for (int i=0;i<8;i++){ ts += rsum[i]; tss += rsq[i]; }
        float mu = ts*(1.f/4096.f);
        rsum[0] = mu;
        rsq[0]  = rsqrtf(tss*(1.f/4096.f)-mu*mu+1e-5f);
    }
    __syncthreads();
    float mu = rsum[0], rr = rsq[0];
    float gm = gamma[cch], bt = beta[cch];
    float* dst = out + (size_t)plane*4096;
    for (int idx=threadIdx.x; idx<4096; idx+=256){
        float v = (buf[idx]-mu)*rr*gm + bt;
        dst[idx] = v > 0.f ? v : 0.01f*v;
    }
}

extern "C" void kernel_launch(void* const* d_in, const int* in_sizes, int n_in,
                              void* d_out, int out_size) {
    const float* x        = (const float*)d_in[0];
    const float* dw_w     = (const float*)d_in[1];
    const float* dw_b     = (const float*)d_in[2];
    const float* scale    = (const float*)d_in[3];
    const float* ln1_g    = (const float*)d_in[4];
    const float* ln1_b    = (const float*)d_in[5];
    const float* in_proj  = (const float*)d_in[6];
    const float* conv_w   = (const float*)d_in[7];
    const float* conv_b   = (const float*)d_in[8];
    const float* x_proj   = (const float*)d_in[9];
    const float* dt_w     = (const float*)d_in[10];
    const float* dt_b     = (const float*)d_in[11];
    const float* A_logs   = (const float*)d_in[12];
    const float* Ds       = (const float*)d_in[13];
    const float* on_g     = (const float*)d_in[14];
    const float* on_b     = (const float*)d_in[15];
    const float* out_proj = (const float*)d_in[16];
    const float* in_gamma = (const float*)d_in[17];
    const float* in_beta  = (const float*)d_in[18];
    float* out = (float*)d_out;

    k1_dwconv  <<<2048, 256>>>(x, dw_w, dw_b, A_logs, Ds);
    k3_inproj  <<<dim3(256,2), 256>>>(in_proj, ln1_g, ln1_b);
    k4_conv    <<<512, 256>>>(conv_w, conv_b);
    k5_xdbl    <<<512, 288>>>(x_proj);
    k6a_scan1  <<<2048, 256>>>(dt_w, dt_b);
    k6b_scan2  <<<256, 256>>>();
    k6c_scan3  <<<2048, 256>>>(dt_w, dt_b);
    k7_comb    <<<4096, 256>>>(on_g, on_b);
    k8_outproj <<<256, 256>>>(out_proj, scale);
    k9_inorm   <<<512, 256>>>(in_gamma, in_beta, out);
}

// round 15
// speedup vs baseline: 1.1638x; 1.0212x over previous
#include <cuda_runtime.h>
#include <cuda_bf16.h>

// B=4,C=128,H=W=64,L=4096, D=64, DI=128, N=16, R=4, K=4. bb=branch*4+b (8), bbk=bb*4+k (32)
// scan: 32 chunks x 128 steps

__device__ float g_xd  [4*128*4096];
__device__ float g_xc  [8*4096*128];
__device__ float g_z   [8*4096*128];
__device__ float g_xc2 [8*4096*128];
__device__ float g_dts [32*4096*4];
__device__ float g_bc  [32*4096*32];
__device__ float g_hc  [32*32*128*16];
__device__ float g_cp  [32*32*128*16];
__device__ float g_hi  [32*32*128*16];
__device__ float g_y4  [32*4096*128];
__device__ float g_g   [8*4096*128];
__device__ float g_xo  [4*128*4096];
__device__ float g_A   [8192];      // -exp(A_logs) * log2(e)
__device__ float g_dsum[128];

#define L2E 1.4426950408889634f
#define LN2 0.6931471805599453f

__device__ __forceinline__ float ex2(float x){
    float y; asm("ex2.approx.ftz.f32 %0, %1;" : "=f"(y) : "f"(x)); return y;
}

__device__ __forceinline__ int pos_map(int k, int t){
    int tt = (k >= 2) ? (4095 - t) : t;
    if (k & 1) tt = ((tt & 63) << 6) | (tt >> 6);
    return tt;
}

// K1: depthwise 3x3 on x (NCHW), smem-tiled, float4 fill; also does prep.
// grid 2048 = (plane, strip4), 256 thr
__global__ void k1_dwconv(const float* __restrict__ x, const float* __restrict__ w,
                          const float* __restrict__ b, const float* __restrict__ A_logs,
                          const float* __restrict__ Ds){
    int gi = blockIdx.x*256 + threadIdx.x;
    if (gi < 8192) g_A[gi] = -expf(A_logs[gi]) * L2E;
    if (gi < 128)  g_dsum[gi] = Ds[gi] + Ds[128+gi] + Ds[256+gi] + Ds[384+gi];

    int plane = blockIdx.x >> 2, strip = blockIdx.x & 3;
    int c = plane & 127, h0 = strip*16;
    __shared__ float t[18][64];
    const float* xp = x + (size_t)plane*4096;
    for (int i=threadIdx.x; i<288; i+=256){
        int r = i >> 4, w4 = i & 15, hh = h0-1+r;
        float4 v = make_float4(0.f,0.f,0.f,0.f);
        if ((unsigned)hh < 64u) v = *(const float4*)(xp + hh*64 + w4*4);
        *(float4*)&t[r][w4*4] = v;
    }
    __syncthreads();
    float w9[9];
    #pragma unroll
    for (int i=0;i<9;i++) w9[i] = w[c*9+i];
    float bv = b[c];
    float* op = g_xd + (size_t)plane*4096 + h0*64;
    for (int i=threadIdx.x; i<1024; i+=256){
        int r = i >> 6, ww = i & 63;
        float acc = bv;
        #pragma unroll
        for (int dh=0; dh<3; dh++){
            #pragma unroll
            for (int dw=-1; dw<=1; dw++){
                int w2 = ww+dw;
                if ((unsigned)w2 < 64u) acc = fmaf(t[r+dh][w2], w9[dh*3+dw+1], acc);
            }
        }
        op[i] = acc;
    }
}

// K3: fused LN(64) + in_proj GEMM [32768,64]x[64,256], 128x128 tile, 8x8/thread.
// float4 fills. grid (256,2), 256 thr
__global__ void k3_inproj(const float* __restrict__ ipw, const float* __restrict__ g1,
                          const float* __restrict__ b1){
    __shared__ float As[32][132];
    __shared__ float Ws[32][132];
    __shared__ float smu[128], srs[128];
    __shared__ float ps[256], pq[256];
    int row0 = blockIdx.x*128, jh = blockIdx.y, tid = threadIdx.x;
    int bb = row0 >> 12, l0 = row0 & 4095;
    int br = bb >> 2, bi = bb & 3;
    const float* src = g_xd + (size_t)(bi*128 + br*64)*4096 + l0;
    {
        int r = tid & 127, half = tid >> 7;
        float s=0.f, ss=0.f;
        #pragma unroll 8
        for (int c=half*32; c<half*32+32; c++){
            float v = src[(size_t)c*4096 + r];
            s += v; ss += v*v;
        }
        ps[tid]=s; pq[tid]=ss;
    }
    __syncthreads();
    if (tid < 128){
        float st = ps[tid]+ps[tid+128], sst = pq[tid]+pq[tid+128];
        float m = st*(1.f/64.f);
        smu[tid]=m; srs[tid]=rsqrtf(sst*(1.f/64.f)-m*m+1e-5f);
    }
    __syncthreads();
    int ct = tid & 15, rt = tid >> 4;
    float acc[8][8];
    #pragma unroll
    for (int i=0;i<8;i++)
        #pragma unroll
        for (int j=0;j<8;j++) acc[i][j]=0.f;
    #pragma unroll
    for (int kc=0; kc<2; kc++){
        // As: 32 c x 128 r, float4 over r (contiguous in src and in As row)
        for (int idx=tid; idx<1024; idx+=256){
            int c = idx >> 5, r4 = idx & 31;
            int cg = kc*32 + c;
            float4 v = *(const float4*)(src + (size_t)cg*4096 + r4*4);
            float gv = g1[cg], bvv = b1[cg];
            float o0 = (v.x-smu[r4*4+0])*srs[r4*4+0]*gv + bvv;
            float o1 = (v.y-smu[r4*4+1])*srs[r4*4+1]*gv + bvv;
            float o2 = (v.z-smu[r4*4+2])*srs[r4*4+2]*gv + bvv;
            float o3 = (v.w-smu[r4*4+3])*srs[r4*4+3]*gv + bvv;
            *(float4*)&As[c][r4*4] = make_float4(o0,o1,o2,o3);
        }
        // Ws: 128 j x 32 c, float4 over c (contiguous in ipw row), transposed store
        for (int idx=tid; idx<1024; idx+=256){
            int j = idx >> 3, c4 = idx & 7;
            float4 v = *(const float4*)(ipw + (size_t)(jh*128+j)*64 + kc*32 + c4*4);
            Ws[c4*4+0][j] = v.x; Ws[c4*4+1][j] = v.y;
            Ws[c4*4+2][j] = v.z; Ws[c4*4+3][j] = v.w;
        }
        __syncthreads();
        #pragma unroll 4
        for (int c=0;c<32;c++){
            float4 a0 = *(const float4*)&As[c][rt*4];
            float4 a1 = *(const float4*)&As[c][rt*4+64];
            float4 w0 = *(const float4*)&Ws[c][ct*4];
            float4 w1 = *(const float4*)&Ws[c][ct*4+64];
            float ar[8] = {a0.x,a0.y,a0.z,a0.w,a1.x,a1.y,a1.z,a1.w};
            float wr[8] = {w0.x,w0.y,w0.z,w0.w,w1.x,w1.y,w1.z,w1.w};
            #pragma unroll
            for (int i=0;i<8;i++)
                #pragma unroll
                for (int j=0;j<8;j++) acc[i][j] = fmaf(ar[i], wr[j], acc[i][j]);
        }
        __syncthreads();
    }
    float* dstbase = (jh==0) ? g_xc : g_z;
    #pragma unroll
    for (int ri=0;ri<8;ri++){
        int r = row0 + rt*4 + (ri&3) + (ri>>2)*64;
        #pragma unroll
        for (int jj=0;jj<2;jj++){
            float4 v = make_float4(acc[ri][jj*4],acc[ri][jj*4+1],acc[ri][jj*4+2],acc[ri][jj*4+3]);
            *(float4*)&dstbase[(size_t)r*128 + ct*4 + jj*64] = v;
        }
    }
}

// K4: depthwise 3x3 + SiLU on xc (pixel-major), smem-tiled, float4 fill.
// grid 512 = (bb8, strip8, cg8), 256 thr
__global__ void k4_conv(const float* __restrict__ cw, const float* __restrict__ cb){
    int bb = blockIdx.x >> 6;
    int strip = (blockIdx.x >> 3) & 7;
    int cg = blockIdx.x & 7;
    int h0 = strip*8, c0 = cg*16;
    __shared__ float t[10][64][16];
    const float* src = g_xc + (size_t)bb*4096*128 + c0;
    for (int i=threadIdx.x; i<2560; i+=256){
        int cl4 = i & 3, ww = (i>>2) & 63, r = i >> 8;
        int hh = h0-1+r;
        float4 v = make_float4(0.f,0.f,0.f,0.f);
        if ((unsigned)hh < 64u) v = *(const float4*)(src + (size_t)(hh*64+ww)*128 + cl4*4);
        *(float4*)&t[r][ww][cl4*4] = v;
    }
    __syncthreads();
    int cl = threadIdx.x & 15, c = c0 + cl;
    float w9[9];
    #pragma unroll
    for (int i=0;i<9;i++) w9[i] = cw[c*9+i];
    float bv = cb[c];
    float* dst = g_xc2 + (size_t)bb*4096*128 + c0 + cl;
    for (int i=threadIdx.x; i<8192; i+=256){
        int ww = (i>>4) & 63, r = i >> 10;
        float acc = bv;
        #pragma unroll
        for (int dh=0; dh<3; dh++){
            #pragma unroll
            for (int dw=-1; dw<=1; dw++){
                int w2 = ww+dw;
                if ((unsigned)w2 < 64u) acc = fmaf(t[r+dh][w2][cl], w9[dh*3+dw+1], acc);
            }
        }
        acc = acc/(1.f+__expf(-acc));
        dst[(size_t)((h0+r)*64+ww)*128] = acc;
    }
}

// K5: x_proj for k-pair {kp, kp+2} sharing one X tile. Tile 128 rows x 72 outs,
// thread = 8 rows x 4 outs, float4 fills. grid 512 = (bb8, kp2, tile32), 288 thr
__global__ void k5_xdbl(const float* __restrict__ xpw){
    __shared__ float Xt[64][132];
    __shared__ float Wt[64][76];
    int bb = blockIdx.x >> 6;
    int kp = (blockIdx.x >> 5) & 1;
    int tile = blockIdx.x & 31;
    int tid = threadIdx.x;
    int t0 = tile*128;
    int ct = tid % 18, rt = tid / 18;
    float acc[8][4];
    #pragma unroll
    for (int i=0;i<8;i++)
        #pragma unroll
        for (int j=0;j<4;j++) acc[i][j]=0.f;
    #pragma unroll
    for (int kc=0; kc<2; kc++){
        // Xt: 128 tl x 64 c, float4 over c (contiguous), transposed store
        for (int idx=tid; idx<2048; idx+=288){
            int tl = idx >> 4, c4 = idx & 15;
            int l = t0 + tl;
            int p = kp ? (((l & 63) << 6) | (l >> 6)) : l;
            float4 v = *(const float4*)(g_xc2 + ((size_t)bb*4096 + p)*128 + kc*64 + c4*4);
            Xt[c4*4+0][tl] = v.x; Xt[c4*4+1][tl] = v.y;
            Xt[c4*4+2][tl] = v.z; Xt[c4*4+3][tl] = v.w;
        }
        // Wt: 72 o x 64 c, float4 over c, transposed store
        for (int idx=tid; idx<1152; idx+=288){
            int o = idx >> 4, c4 = idx & 15;
            int kk = (o < 36) ? kp : (kp+2);
            int oo = (o < 36) ? o : (o-36);
            float4 v = *(const float4*)(xpw + (size_t)(kk*36+oo)*128 + kc*64 + c4*4);
            Wt[c4*4+0][o] = v.x; Wt[c4*4+1][o] = v.y;
            Wt[c4*4+2][o] = v.z; Wt[c4*4+3][o] = v.w;
        }
        __syncthreads();
        #pragma unroll 4
        for (int c=0;c<64;c++){
            float4 x0 = *(const float4*)&Xt[c][rt*8];
            float4 x1 = *(const float4*)&Xt[c][rt*8+4];
            float4 wv = *(const float4*)&Wt[c][ct*4];
            float xr[8] = {x0.x,x0.y,x0.z,x0.w,x1.x,x1.y,x1.z,x1.w};
            float wr[4] = {wv.x,wv.y,wv.z,wv.w};
            #pragma unroll
            for (int i=0;i<8;i++)
                #pragma unroll
                for (int j=0;j<4;j++) acc[i][j] = fmaf(xr[i], wr[j], acc[i][j]);
        }
        __syncthreads();
    }
    bool hi = (ct >= 9);
    int o4 = hi ? (ct-9)*4 : ct*4;
    int bbk = bb*4 + kp + (hi ? 2 : 0);
    #pragma unroll
    for (int i=0;i<8;i++){
        int tl = rt*8 + i;
        int t = hi ? (4095 - (t0+tl)) : (t0+tl);
        float4 v = make_float4(acc[i][0],acc[i][1],acc[i][2],acc[i][3]);
        if (o4 == 0)
            *(float4*)&g_dts[((size_t)bbk*4096 + t)*4] = v;
        else
            *(float4*)&g_bc[((size_t)bbk*4096 + t)*32 + (o4-4)] = v;
    }
}

// K6a: pass1 chunk-local scan (128 steps), exp2-domain MUFU, prefetch.
// warp=(bbk,dg,chunk32). grid 2048, 256 thr
__global__ void k6a_scan1(const float* __restrict__ dtw, const float* __restrict__ dtb){
    int gw = blockIdx.x*8 + (threadIdx.x >> 5);
    int lane = threadIdx.x & 31;
    int chunk = gw & 31, dg = (gw >> 5) & 15, bbk = gw >> 9;
    int bb = bbk >> 2, k = bbk & 3;
    int dl = lane >> 2, sg = lane & 3, d = dg*8 + dl;
    float4 Av = *(const float4*)(g_A + (size_t)(k*128+d)*16 + sg*4);
    float4 wv = *(const float4*)(dtw + (k*128+d)*4);
    wv.x *= L2E; wv.y *= L2E; wv.z *= L2E; wv.w *= L2E;
    float bvb = dtb[k*128+d] * L2E;
    float h0=0,h1=0,h2=0,h3=0, dsum=0;
    int t0c = chunk*128;
    const float4* dts4 = (const float4*)(g_dts + ((size_t)bbk*4096 + t0c)*4);
    const float* bc  = g_bc + ((size_t)bbk*4096 + t0c)*32 + sg*4;
    const float* ubb = g_xc2 + (size_t)bb*4096*128 + d;
    float4 qn = dts4[sg];
    float un = ubb[(size_t)pos_map(k, t0c + sg)*128];
    for (int g4=0; g4<32; g4++){
        float4 q = qn; float uu = un;
        if (g4 < 31){
            qn = dts4[(g4+1)*4 + sg];
            un = ubb[(size_t)pos_map(k, t0c + (g4+1)*4 + sg)*128];
        }
        float x2 = q.x*wv.x + q.y*wv.y + q.z*wv.z + q.w*wv.w + bvb;
        float sp = (x2 > 28.85f) ? x2*LN2 : LN2*__log2f(1.f+ex2(x2));
        float duu = sp * uu;
        #pragma unroll
        for (int j=0;j<4;j++){
            int t = g4*4 + j;
            float delta = __shfl_sync(0xffffffffu, sp, j, 4);
            float du    = __shfl_sync(0xffffffffu, duu, j, 4);
            float4 B = *(const float4*)(bc + (size_t)t*32);
            dsum += delta;
            float a0 = ex2(delta*Av.x), a1 = ex2(delta*Av.y);
            float a2 = ex2(delta*Av.z), a3 = ex2(delta*Av.w);
            h0 = fmaf(a0,h0,du*B.x); h1 = fmaf(a1,h1,du*B.y);
            h2 = fmaf(a2,h2,du*B.z); h3 = fmaf(a3,h3,du*B.w);
        }
    }
    size_t so = ((size_t)(bbk*32+chunk)*128 + d)*16 + sg*4;
    *(float4*)(g_hc + so) = make_float4(h0,h1,h2,h3);
    *(float4*)(g_cp + so) = make_float4(ex2(dsum*Av.x),ex2(dsum*Av.y),
                                        ex2(dsum*Av.z),ex2(dsum*Av.w));
}

// K6b: sequential scan over 32 chunk summaries, loads prefetched. grid 256, 256 thr
__global__ void k6b_scan2(){
    int idx = blockIdx.x*256 + threadIdx.x;
    int bbk = idx >> 11, rem = idx & 2047;
    size_t base = (size_t)bbk*32*2048 + rem;
    float H = 0.f;
    float cp = g_cp[base], hc = g_hc[base];
    #pragma unroll
    for (int c=0; c<32; c++){
        size_t o = base + (size_t)c*2048;
        float cpn = 0.f, hcn = 0.f;
        if (c < 31){ cpn = g_cp[o+2048]; hcn = g_hc[o+2048]; }
        g_hi[o] = H;
        H = fmaf(cp, H, hc);
        cp = cpn; hc = hcn;
    }
}

// K6c: pass3 with incoming state, emit y=C.h, exp2-domain MUFU, prefetch.
// grid 2048, 256 thr
__global__ void k6c_scan3(const float* __restrict__ dtw, const float* __restrict__ dtb){
    int gw = blockIdx.x*8 + (threadIdx.x >> 5);
    int lane = threadIdx.x & 31;
    int chunk = gw & 31, dg = (gw >> 5) & 15, bbk = gw >> 9;
    int bb = bbk >> 2, k = bbk & 3;
    int dl = lane >> 2, sg = lane & 3, d = dg*8 + dl;
    float4 Av = *(const float4*)(g_A + (size_t)(k*128+d)*16 + sg*4);
    float4 wv = *(const float4*)(dtw + (k*128+d)*4);
    wv.x *= L2E; wv.y *= L2E; wv.z *= L2E; wv.w *= L2E;
    float bvb = dtb[k*128+d] * L2E;
    size_t so = ((size_t)(bbk*32+chunk)*128 + d)*16 + sg*4;
    float4 hi = *(const float4*)(g_hi + so);
    float h0=hi.x, h1=hi.y, h2=hi.z, h3=hi.w;
    int t0c = chunk*128;
    const float4* dts4 = (const float4*)(g_dts + ((size_t)bbk*4096 + t0c)*4);
    const float* bc  = g_bc + ((size_t)bbk*4096 + t0c)*32;
    const float* ubb = g_xc2 + (size_t)bb*4096*128 + d;
    float* yo = g_y4 + ((size_t)bbk*4096 + t0c)*128 + d;
    float4 qn = dts4[sg];
    float un = ubb[(size_t)pos_map(k, t0c + sg)*128];
    for (int g4=0; g4<32; g4++){
        float4 q = qn; float uu = un;
        if (g4 < 31){
            qn = dts4[(g4+1)*4 + sg];
            un = ubb[(size_t)pos_map(k, t0c + (g4+1)*4 + sg)*128];
        }
        float x2 = q.x*wv.x + q.y*wv.y + q.z*wv.z + q.w*wv.w + bvb;
        float sp = (x2 > 28.85f) ? x2*LN2 : LN2*__log2f(1.f+ex2(x2));
        float duu = sp * uu;
        #pragma unroll
        for (int j=0;j<4;j++){
            int t = g4*4 + j;
            float delta = __shfl_sync(0xffffffffu, sp, j, 4);
            float du    = __shfl_sync(0xffffffffu, duu, j, 4);
            float4 B = *(const float4*)(bc + (size_t)t*32 + sg*4);
            float4 C = *(const float4*)(bc + (size_t)t*32 + 16 + sg*4);
            float a0 = ex2(delta*Av.x), a1 = ex2(delta*Av.y);
            float a2 = ex2(delta*Av.z), a3 = ex2(delta*Av.w);
            h0 = fmaf(a0,h0,du*B.x); h1 = fmaf(a1,h1,du*B.y);
            h2 = fmaf(a2,h2,du*B.z); h3 = fmaf(a3,h3,du*B.w);
            float acc = h0*C.x + h1*C.y + h2*C.z + h3*C.w;
            acc += __shfl_xor_sync(0xffffffffu, acc, 1);
            acc += __shfl_xor_sync(0xffffffffu, acc, 2);
            if (sg == 0) yo[(size_t)t*128] = acc;
        }
    }
}

// K7: combine 4 dirs + Dsum*u + LN(128) + silu(z) gate, float4 lanes.
// warp/pixel. grid 4096, 256 thr
__global__ void k7_comb(const float* __restrict__ ong, const float* __restrict__ onb){
    int wid = threadIdx.x >> 5, lane = threadIdx.x & 31;
    int gp = blockIdx.x*8 + wid;
    int bb = gp >> 12, l = gp & 4095;
    float4 v = *(const float4*)&g_dsum[lane*4];
    float4 xr = *(const float4*)&g_xc2[((size_t)bb*4096 + l)*128 + lane*4];
    v.x *= xr.x; v.y *= xr.y; v.z *= xr.z; v.w *= xr.w;
    #pragma unroll
    for (int k=0;k<4;k++){
        int t = pos_map(k,l);
        float4 r = *(const float4*)&g_y4[(((size_t)(bb*4+k)*4096 + t)*128) + lane*4];
        v.x += r.x; v.y += r.y; v.z += r.z; v.w += r.w;
    }
    float s = v.x+v.y+v.z+v.w;
    float ss = v.x*v.x+v.y*v.y+v.z*v.z+v.w*v.w;
    #pragma unroll
    for (int o=16;o;o>>=1){ s += __shfl_xor_sync(0xffffffffu,s,o); ss += __shfl_xor_sync(0xffffffffu,ss,o); }
    float mu = s*(1.f/128.f);
    float rs = rsqrtf(ss*(1.f/128.f)-mu*mu+1e-5f);
    float4 z4 = *(const float4*)&g_z[((size_t)bb*4096+l)*128 + lane*4];
    float4 gg = *(const float4*)&ong[lane*4];
    float4 bb4 = *(const float4*)&onb[lane*4];
    float4 o4;
    o4.x = ((v.x-mu)*rs*gg.x+bb4.x) * (z4.x/(1.f+__expf(-z4.x)));
    o4.y = ((v.y-mu)*rs*gg.y+bb4.y) * (z4.y/(1.f+__expf(-z4.y)));
    o4.z = ((v.z-mu)*rs*gg.z+bb4.z) * (z4.z/(1.f+__expf(-z4.z)));
    o4.w = ((v.w-mu)*rs*gg.w+bb4.w) * (z4.w/(1.f+__expf(-z4.w)));
    *(float4*)&g_g[((size_t)bb*4096+l)*128 + lane*4] = o4;
}

// K8: out_proj [32768,128]x[128,64] + residual -> NCHW. 128x64 tile, 8x4/thread,
// K-chunk 32, float4 fills. grid 256, 256 thr
__global__ void k8_outproj(const float* __restrict__ opw, const float* __restrict__ scale){
    __shared__ float Xs[32][132];
    __shared__ float Ws[32][72];
    int row0 = blockIdx.x*128, tid = threadIdx.x;
    int ct = tid & 15, rt = tid >> 4;
    float acc[8][4];
    #pragma unroll
    for (int i=0;i<8;i++)
        #pragma unroll
        for (int j=0;j<4;j++) acc[i][j]=0.f;
    #pragma unroll
    for (int kc=0; kc<4; kc++){
        for (int idx=tid; idx<1024; idx+=256){
            int r = idx >> 3, c4 = idx & 7;
            float4 v = *(const float4*)(g_g + (size_t)(row0+r)*128 + kc*32 + c4*4);
            Xs[c4*4+0][r] = v.x; Xs[c4*4+1][r] = v.y;
            Xs[c4*4+2][r] = v.z; Xs[c4*4+3][r] = v.w;
        }
        for (int idx=tid; idx<512; idx+=256){
            int j = idx >> 3, c4 = idx & 7;
            float4 v = *(const float4*)(opw + (size_t)j*128 + kc*32 + c4*4);
            Ws[c4*4+0][j] = v.x; Ws[c4*4+1][j] = v.y;
            Ws[c4*4+2][j] = v.z; Ws[c4*4+3][j] = v.w;
        }
        __syncthreads();
        #pragma unroll 4
        for (int c=0;c<32;c++){
            float4 x0 = *(const float4*)&Xs[c][rt*4];
            float4 x1 = *(const float4*)&Xs[c][rt*4+64];
            float4 w0 = *(const float4*)&Ws[c][ct*4];
            float xr[8] = {x0.x,x0.y,x0.z,x0.w,x1.x,x1.y,x1.z,x1.w};
            float wr[4] = {w0.x,w0.y,w0.z,w0.w};
            #pragma unroll
            for (int i=0;i<8;i++)
                #pragma unroll
                for (int j=0;j<4;j++) acc[i][j] = fmaf(xr[i], wr[j], acc[i][j]);
        }
        __syncthreads();
    }
    float s1 = scale[0] + 1.f;
    int bb = row0 >> 12, l0 = (row0 & 4095) + rt*4;
    #pragma unroll
    for (int jo=0;jo<4;jo++){
        int j = ct*4 + jo;
        int plane = (bb&3)*128 + (bb>>2)*64 + j;
        #pragma unroll
        for (int half=0; half<2; half++){
            int l = l0 + half*64;
            float4 xd4 = *(const float4*)(g_xd + (size_t)plane*4096 + l);
            float4 o4;
            o4.x = fmaf(s1, xd4.x, acc[half*4+0][jo]);
            o4.y = fmaf(s1, xd4.y, acc[half*4+1][jo]);
            o4.z = fmaf(s1, xd4.z, acc[half*4+2][jo]);
            o4.w = fmaf(s1, xd4.w, acc[half*4+3][jo]);
            *(float4*)(g_xo + (size_t)plane*4096 + l) = o4;
        }
    }
}

// K9: instance norm over HW + leaky relu. grid 512 planes, 256 thr
__global__ void k9_inorm(const float* __restrict__ gamma, const float* __restrict__ beta,
                         float* __restrict__ out){
    __shared__ float buf[4096];
    __shared__ float rsum[8], rsq[8];
    int plane = blockIdx.x, cch = plane & 127;
    const float* src = g_xo + (size_t)plane*4096;
    float s=0.f, ss=0.f;
    for (int idx=threadIdx.x; idx<1024; idx+=256){
        float4 v = ((const float4*)src)[idx];
        ((float4*)buf)[idx] = v;
        s += v.x+v.y+v.z+v.w;
        ss += v.x*v.x+v.y*v.y+v.z*v.z+v.w*v.w;
    }
    #pragma unroll
    for (int o=16;o;o>>=1){ s += __shfl_xor_sync(0xffffffffu,s,o); ss += __shfl_xor_sync(0xffffffffu,ss,o); }
    int wid = threadIdx.x >> 5;
    if ((threadIdx.x & 31) == 0){ rsum[wid]=s; rsq[wid]=ss; }
    __syncthreads();
    if (threadIdx.x == 0){
        float ts=0.f, tss=0.f;
        #pragma unroll
        for (int i=0;i<8;i++){ ts += rsum[i]; tss += rsq[i]; }
        float mu = ts*(1.f/4096.f);
        rsum[0] = mu;
        rsq[0]  = rsqrtf(tss*(1.f/4096.f)-mu*mu+1e-5f);
    }
    __syncthreads();
    float mu = rsum[0], rr = rsq[0];
    float gm = gamma[cch], bt = beta[cch];
    float* dst = out + (size_t)plane*4096;
    for (int idx=threadIdx.x; idx<4096; idx+=256){
        float v = (buf[idx]-mu)*rr*gm + bt;
        dst[idx] = v > 0.f ? v : 0.01f*v;
    }
}

extern "C" void kernel_launch(void* const* d_in, const int* in_sizes, int n_in,
                              void* d_out, int out_size) {
    const float* x        = (const float*)d_in[0];
    const float* dw_w     = (const float*)d_in[1];
    const float* dw_b     = (const float*)d_in[2];
    const float* scale    = (const float*)d_in[3];
    const float* ln1_g    = (const float*)d_in[4];
    const float* ln1_b    = (const float*)d_in[5];
    const float* in_proj  = (const float*)d_in[6];
    const float* conv_w   = (const float*)d_in[7];
    const float* conv_b   = (const float*)d_in[8];
    const float* x_proj   = (const float*)d_in[9];
    const float* dt_w     = (const float*)d_in[10];
    const float* dt_b     = (const float*)d_in[11];
    const float* A_logs   = (const float*)d_in[12];
    const float* Ds       = (const float*)d_in[13];
    const float* on_g     = (const float*)d_in[14];
    const float* on_b     = (const float*)d_in[15];
    const float* out_proj = (const float*)d_in[16];
    const float* in_gamma = (const float*)d_in[17];
    const float* in_beta  = (const float*)d_in[18];
    float* out = (float*)d_out;

    k1_dwconv  <<<2048, 256>>>(x, dw_w, dw_b, A_logs, Ds);
    k3_inproj  <<<dim3(256,2), 256>>>(in_proj, ln1_g, ln1_b);
    k4_conv    <<<512, 256>>>(conv_w, conv_b);
    k5_xdbl    <<<512, 288>>>(x_proj);
    k6a_scan1  <<<2048, 256>>>(dt_w, dt_b);
    k6b_scan2  <<<256, 256>>>();
    k6c_scan3  <<<2048, 256>>>(dt_w, dt_b);
    k7_comb    <<<4096, 256>>>(on_g, on_b);
    k8_outproj <<<256, 256>>>(out_proj, scale);
    k9_inorm   <<<512, 256>>>(in_gamma, in_beta, out);
}